// round 15
// baseline (speedup 1.0000x reference)
#include <cuda_runtime.h>
#include <cuda_bf16.h>
#include <math.h>

#define Bb   4
#define Tt   512
#define Dd   1024
#define Vv   32000
#define Pp   256
#define Ss   4096
#define KDim 64
#define VDim 64
#define TopK 4
#define Hh   1024
#define MACW 1536
#define UPB  7
#define SLOT 32

typedef unsigned long long u64;

// ---------------- device scratch ----------------
__device__ __align__(16) float g_mac[Bb * Tt * MACW];
__device__ __align__(16) float g_enc[Bb * Tt * Dd];
__device__ __align__(16) float g_enc_cur[Bb * Dd];
__device__ __align__(16) float g_h[2 * Bb * Hh];
__device__ __align__(16) float g_l[2 * Bb * Hh];
__device__ __align__(16) float g_wcomb[3 * Hh * Hh];   // lWi[:,1024:] @ h2c
__device__ __align__(16) float g_bcomb[3 * Hh];        // lbi + lWi2 @ h2cb
__device__ int g_viol[4];
__device__ unsigned g_slots[256 * SLOT];

// ---------------- helpers ----------------
__device__ __forceinline__ float warp_sum(float v) {
#pragma unroll
    for (int o = 16; o > 0; o >>= 1) v += __shfl_xor_sync(0xffffffffu, v, o);
    return v;
}
__device__ __forceinline__ float d4(float4 a, float4 b) {
    return a.x * b.x + a.y * b.y + a.z * b.z + a.w * b.w;
}
__device__ __forceinline__ float sigm(float x) { return 1.0f / (1.0f + expf(-x)); }
__device__ __forceinline__ float gelu_exact(float x) {
    return 0.5f * x * (1.0f + erff(x * 0.70710678118654752f));
}
__device__ __forceinline__ u64 f2fma(u64 a, u64 b, u64 c) {
    asm("fma.rn.f32x2 %0, %1, %2, %3;" : "=l"(c) : "l"(a), "l"(b), "l"(c));
    return c;
}
__device__ __forceinline__ float f2red(u64 a) {
    float lo, hi;
    asm("mov.b64 {%0, %1}, %2;" : "=f"(lo), "=f"(hi) : "l"(a));
    return lo + hi;
}
__device__ __forceinline__ u64 f2dup(float x) {
    u64 r;
    asm("mov.b64 %0, {%1, %1};" : "=l"(r) : "r"(__float_as_uint(x)));
    return r;
}
__device__ __forceinline__ float4 ldcv4(const float* p) {
    float4 v;
    asm volatile("ld.global.cv.v4.f32 {%0,%1,%2,%3}, [%4];"
                 : "=f"(v.x), "=f"(v.y), "=f"(v.z), "=f"(v.w) : "l"(p));
    return v;
}
__device__ __forceinline__ void st_rel(unsigned* p, unsigned v) {
    asm volatile("st.global.release.gpu.u32 [%0], %1;" :: "l"(p), "r"(v) : "memory");
}
__device__ __forceinline__ unsigned ld_acq(const unsigned* p) {
    unsigned v;
    asm volatile("ld.global.acquire.gpu.u32 %0, [%1];" : "=r"(v) : "l"(p) : "memory");
    return v;
}

// stage 4 batch-rows of 1024 floats into smem [4][1024] via .cv (blockDim==512)
__device__ __forceinline__ void stage(float* dst, const float* src, long bs) {
    int tid = threadIdx.x;
#pragma unroll
    for (int rr = 0; rr < 2; rr++) {
        int f = tid + rr * 512;
        int b = f >> 8, k = f & 255;
        ((float4*)dst)[f] = ldcv4(src + (long)b * bs + k * 4);
    }
}

// 3 weight rows x 4 batch vectors, HALF of K (512 floats), packed f32x2.
// half selects K-range [half*512, half*512+512). out = warp-reduced partials.
__device__ __forceinline__ void sdot3x4h(const float* __restrict__ w0,
                                         const float* __restrict__ w1,
                                         const float* __restrict__ w2,
                                         const float* xs, int half, float out[12]) {
    const ulonglong2* W0 = (const ulonglong2*)w0 + half * 128;
    const ulonglong2* W1 = (const ulonglong2*)w1 + half * 128;
    const ulonglong2* W2 = (const ulonglong2*)w2 + half * 128;
    const ulonglong2* X0 = (const ulonglong2*)xs + half * 128;
    const ulonglong2* X1 = X0 + 256;
    const ulonglong2* X2 = X0 + 512;
    const ulonglong2* X3 = X0 + 768;
    int lane = threadIdx.x & 31;
    u64 acc[12] = {};
#pragma unroll
    for (int u = 0; u < 4; u++) {
        int i = lane + u * 32;
        ulonglong2 a0 = W0[i], a1 = W1[i], a2 = W2[i];
        ulonglong2 x0 = X0[i], x1 = X1[i], x2 = X2[i], x3 = X3[i];
        acc[0] = f2fma(a0.x, x0.x, acc[0]); acc[0] = f2fma(a0.y, x0.y, acc[0]);
        acc[1] = f2fma(a0.x, x1.x, acc[1]); acc[1] = f2fma(a0.y, x1.y, acc[1]);
        acc[2] = f2fma(a0.x, x2.x, acc[2]); acc[2] = f2fma(a0.y, x2.y, acc[2]);
        acc[3] = f2fma(a0.x, x3.x, acc[3]); acc[3] = f2fma(a0.y, x3.y, acc[3]);
        acc[4] = f2fma(a1.x, x0.x, acc[4]); acc[4] = f2fma(a1.y, x0.y, acc[4]);
        acc[5] = f2fma(a1.x, x1.x, acc[5]); acc[5] = f2fma(a1.y, x1.y, acc[5]);
        acc[6] = f2fma(a1.x, x2.x, acc[6]); acc[6] = f2fma(a1.y, x2.y, acc[6]);
        acc[7] = f2fma(a1.x, x3.x, acc[7]); acc[7] = f2fma(a1.y, x3.y, acc[7]);
        acc[8] = f2fma(a2.x, x0.x, acc[8]); acc[8] = f2fma(a2.y, x0.y, acc[8]);
        acc[9] = f2fma(a2.x, x1.x, acc[9]); acc[9] = f2fma(a2.y, x1.y, acc[9]);
        acc[10]= f2fma(a2.x, x2.x, acc[10]);acc[10]= f2fma(a2.y, x2.y, acc[10]);
        acc[11]= f2fma(a2.x, x3.x, acc[11]);acc[11]= f2fma(a2.y, x3.y, acc[11]);
    }
#pragma unroll
    for (int k = 0; k < 12; k++) out[k] = warp_sum(f2red(acc[k]));
}

// 1 weight row x 4 batch vectors, half of K
__device__ __forceinline__ void sdot1x4h(const float* __restrict__ w,
                                         const float* xs, int half, float out[4]) {
    const ulonglong2* W  = (const ulonglong2*)w + half * 128;
    const ulonglong2* X0 = (const ulonglong2*)xs + half * 128;
    const ulonglong2* X1 = X0 + 256;
    const ulonglong2* X2 = X0 + 512;
    const ulonglong2* X3 = X0 + 768;
    int lane = threadIdx.x & 31;
    u64 acc[4] = {};
#pragma unroll
    for (int u = 0; u < 4; u++) {
        int i = lane + u * 32;
        ulonglong2 wv = W[i];
        ulonglong2 x0 = X0[i], x1 = X1[i], x2 = X2[i], x3 = X3[i];
        acc[0] = f2fma(wv.x, x0.x, acc[0]); acc[0] = f2fma(wv.y, x0.y, acc[0]);
        acc[1] = f2fma(wv.x, x1.x, acc[1]); acc[1] = f2fma(wv.y, x1.y, acc[1]);
        acc[2] = f2fma(wv.x, x2.x, acc[2]); acc[2] = f2fma(wv.y, x2.y, acc[2]);
        acc[3] = f2fma(wv.x, x3.x, acc[3]); acc[3] = f2fma(wv.y, x3.y, acc[3]);
    }
#pragma unroll
    for (int k = 0; k < 4; k++) out[k] = warp_sum(f2red(acc[k]));
}

// grid barrier (release/acquire, padded slots)
__device__ __forceinline__ void gbar(int nb, unsigned& gen) {
    gen++;
    __syncthreads();
    if (threadIdx.x == 0) st_rel(&g_slots[blockIdx.x * SLOT], gen);
    if ((int)threadIdx.x < nb)
        while (ld_acq(&g_slots[threadIdx.x * SLOT]) < gen) { }
    __syncthreads();
}
// barrier + per-block violation aggregation into g_viol[it]
__device__ __forceinline__ void gbar_v(int nb, unsigned& gen, int it, int* s_vio) {
    gen++;
    __syncthreads();
    if (threadIdx.x == 0) {
        int v = 0;
#pragma unroll
        for (int w = 0; w < 16; w++) v |= s_vio[w];
        if (v) atomicOr(&g_viol[it], 1);
        st_rel(&g_slots[blockIdx.x * SLOT], gen);
    }
    if ((int)threadIdx.x < nb && threadIdx.x != 0)
        while (ld_acq(&g_slots[threadIdx.x * SLOT]) < gen) { }
    if (threadIdx.x == 0)
        while (ld_acq(&g_slots[0]) < gen) { }
    __syncthreads();
}

// ---------------- kernels ----------------
__global__ void k_init() {
    int i = blockIdx.x * blockDim.x + threadIdx.x;
    if (i < 256 * SLOT) g_slots[i] = 0;
    if (i < 4) g_viol[i] = 0;
    for (int k = i; k < 2 * Bb * Hh; k += gridDim.x * blockDim.x) {
        g_h[k] = 0.f; g_l[k] = 0.f;
    }
}

__global__ void k_mac(const int* __restrict__ ids, const float* __restrict__ tok,
                      const float* __restrict__ pos, const float* __restrict__ pers,
                      const float* __restrict__ keys, const float* __restrict__ lvals,
                      const float* __restrict__ qw,
                      float* __restrict__ out_vals, float* __restrict__ out_idx) {
    __shared__ __align__(16) float sx[Dd];
    __shared__ __align__(16) float sq[KDim];
    __shared__ float ssim[Ss];
    __shared__ float rv[256];
    __shared__ int   ri[256];
    __shared__ int   s_top[TopK];

    int t = blockIdx.x, b = blockIdx.y;
    int tid = threadIdx.x;
    long row = (long)b * Tt + t;
    float* macrow = g_mac + row * MACW;

    int id = ids[b * Tt + t];
    for (int d = tid; d < Dd; d += 256) {
        float v = tok[(size_t)id * Dd + d] + pos[(size_t)t * Dd + d];
        sx[d] = v;
        macrow[d] = v;
    }
    for (int p = tid; p < Pp; p += 256) macrow[Dd + p] = pers[p];
    __syncthreads();

    int wid = tid >> 5, lane = tid & 31;
    for (int o = wid; o < KDim; o += 8) {
        const float4* W = (const float4*)(qw + (size_t)o * Dd);
        const float4* X = (const float4*)sx;
        float s = 0.f;
        for (int i = lane; i < Dd / 4; i += 32) s += d4(W[i], X[i]);
        s = warp_sum(s);
        if (lane == 0) sq[o] = s;
    }
    __syncthreads();

    for (int i = tid; i < Ss; i += 256) {
        const float4* Kr = (const float4*)(keys + (size_t)i * KDim);
        const float4* Q  = (const float4*)sq;
        float s = 0.f;
#pragma unroll
        for (int q = 0; q < 16; q++) s += d4(Kr[q], Q[q]);
        ssim[i] = s;
    }
    __syncthreads();

    for (int kk = 0; kk < TopK; kk++) {
        float bv = -1e30f; int bi2 = 0x7fffffff;
        for (int i = tid; i < Ss; i += 256) {
            float v = ssim[i];
            if (v > bv || (v == bv && i < bi2)) { bv = v; bi2 = i; }
        }
        rv[tid] = bv; ri[tid] = bi2;
        __syncthreads();
        for (int s = 128; s > 0; s >>= 1) {
            if (tid < s) {
                if (rv[tid + s] > rv[tid] ||
                    (rv[tid + s] == rv[tid] && ri[tid + s] < ri[tid])) {
                    rv[tid] = rv[tid + s]; ri[tid] = ri[tid + s];
                }
            }
            __syncthreads();
        }
        if (tid == 0) { s_top[kk] = ri[0]; ssim[ri[0]] = -1e38f; }
        __syncthreads();
    }

    for (int kk = 0; kk < TopK; kk++) {
        int ix = s_top[kk];
        for (int v = tid; v < VDim; v += 256) {
            float val = lvals[(size_t)ix * VDim + v];
            macrow[Dd + Pp + kk * VDim + v] = val;
            if (out_vals) out_vals[(row * TopK + kk) * VDim + v] = val;
        }
        if (tid == 0 && out_idx) out_idx[row * TopK + kk] = (float)ix;
    }
}

// C[M,N] = A[M,K] * B[N,K]^T ; epi=1 -> bias + exact gelu  (f32x2 inner)
__global__ void k_gemm(const float* __restrict__ A, const float* __restrict__ Bm,
                       const float* __restrict__ bias, float* __restrict__ C,
                       int M, int N, int Kd, int epi) {
    __shared__ __align__(16) float As[16][68];
    __shared__ __align__(16) float Bs[16][68];
    int tid = threadIdx.x;
    int tx = tid & 15, ty = tid >> 4;
    int q = tid & 3,  r  = tid >> 2;
    int m0 = blockIdx.y * 64, n0 = blockIdx.x * 64;
    u64 acc2[4][2] = {};
    for (int kt = 0; kt < Kd; kt += 16) {
        float4 av = *(const float4*)&A[(size_t)(m0 + r) * Kd + kt + q * 4];
        float4 bv = *(const float4*)&Bm[(size_t)(n0 + r) * Kd + kt + q * 4];
        As[q*4+0][r]=av.x; As[q*4+1][r]=av.y; As[q*4+2][r]=av.z; As[q*4+3][r]=av.w;
        Bs[q*4+0][r]=bv.x; Bs[q*4+1][r]=bv.y; Bs[q*4+2][r]=bv.z; Bs[q*4+3][r]=bv.w;
        __syncthreads();
#pragma unroll
        for (int kk = 0; kk < 16; kk++) {
            float4 a = *(const float4*)&As[kk][ty * 4];
            ulonglong2 bp = *(const ulonglong2*)&Bs[kk][tx * 4];
            u64 a0 = f2dup(a.x), a1 = f2dup(a.y), a2 = f2dup(a.z), a3 = f2dup(a.w);
            acc2[0][0] = f2fma(a0, bp.x, acc2[0][0]); acc2[0][1] = f2fma(a0, bp.y, acc2[0][1]);
            acc2[1][0] = f2fma(a1, bp.x, acc2[1][0]); acc2[1][1] = f2fma(a1, bp.y, acc2[1][1]);
            acc2[2][0] = f2fma(a2, bp.x, acc2[2][0]); acc2[2][1] = f2fma(a2, bp.y, acc2[2][1]);
            acc2[3][0] = f2fma(a3, bp.x, acc2[3][0]); acc2[3][1] = f2fma(a3, bp.y, acc2[3][1]);
        }
        __syncthreads();
    }
#pragma unroll
    for (int i = 0; i < 4; i++) {
        int m = m0 + ty * 4 + i;
#pragma unroll
        for (int jh = 0; jh < 2; jh++) {
            float lo, hi;
            asm("mov.b64 {%0, %1}, %2;" : "=f"(lo), "=f"(hi) : "l"(acc2[i][jh]));
            int n = n0 + tx * 4 + jh * 2;
            float v0 = lo, v1 = hi;
            if (epi) {
                v0 = gelu_exact(v0 + bias[n]);
                v1 = gelu_exact(v1 + bias[n + 1]);
            }
            C[(size_t)m * N + n]     = v0;
            C[(size_t)m * N + n + 1] = v1;
        }
    }
}

// C[3072][1024] = A(rows stride rstride, col offset coff) @ Bm[1024,1024]
__global__ void k_comb(const float* __restrict__ A, long rstride, long coff,
                       const float* __restrict__ Bm, float* __restrict__ C) {
    __shared__ __align__(16) float As[16][68];
    __shared__ __align__(16) float Bs[16][68];
    int tid = threadIdx.x;
    int tx = tid & 15, ty = tid >> 4;
    int q = tid & 3,  r  = tid >> 2;
    int rr = tid >> 4, cc = tid & 15;
    int n0 = blockIdx.x * 64, m0 = blockIdx.y * 64;
    float acc[4][4] = {};
    for (int d0 = 0; d0 < Hh; d0 += 16) {
        float4 av = *(const float4*)&A[(size_t)(m0 + r) * rstride + coff + d0 + q * 4];
        As[q*4+0][r]=av.x; As[q*4+1][r]=av.y; As[q*4+2][r]=av.z; As[q*4+3][r]=av.w;
        float4 bv = *(const float4*)&Bm[(size_t)(d0 + rr) * Hh + n0 + cc * 4];
        *(float4*)&Bs[rr][cc * 4] = bv;
        __syncthreads();
#pragma unroll
        for (int kk = 0; kk < 16; kk++) {
            float4 a = *(const float4*)&As[kk][ty * 4];
            float4 b = *(const float4*)&Bs[kk][tx * 4];
            acc[0][0]+=a.x*b.x; acc[0][1]+=a.x*b.y; acc[0][2]+=a.x*b.z; acc[0][3]+=a.x*b.w;
            acc[1][0]+=a.y*b.x; acc[1][1]+=a.y*b.y; acc[1][2]+=a.y*b.z; acc[1][3]+=a.y*b.w;
            acc[2][0]+=a.z*b.x; acc[2][1]+=a.z*b.y; acc[2][2]+=a.z*b.z; acc[2][3]+=a.z*b.w;
            acc[3][0]+=a.w*b.x; acc[3][1]+=a.w*b.y; acc[3][2]+=a.w*b.z; acc[3][3]+=a.w*b.w;
        }
        __syncthreads();
    }
#pragma unroll
    for (int i = 0; i < 4; i++)
#pragma unroll
        for (int j = 0; j < 4; j++)
            C[(size_t)(m0 + ty * 4 + i) * Hh + n0 + tx * 4 + j] = acc[i][j];
}

// out[r] = addb[r] + dot(W[r*rstride+coff .. +1024], v)
__global__ void k_vdot(const float* __restrict__ W, long rstride, long coff,
                       const float* __restrict__ v, const float* __restrict__ addb,
                       float* __restrict__ out) {
    int r = (blockIdx.x * blockDim.x + threadIdx.x) >> 5;
    if (r >= 3 * Hh) return;
    const float4* Wr = (const float4*)(W + (size_t)r * rstride + coff);
    const float4* X  = (const float4*)v;
    int lane = threadIdx.x & 31;
    float s = 0.f;
    for (int i = lane; i < 256; i += 32) s += d4(Wr[i], X[i]);
    s = warp_sum(s);
    if (lane == 0) out[r] = (addb ? addb[r] : 0.f) + s;
}

// ---- persistent recurrence: 512 threads, warp-pair (K-split) per hidden unit ----
__global__ __launch_bounds__(512, 1)
void k_seq(int nb,
           const float* __restrict__ hWi, const float* __restrict__ hbi,
           const float* __restrict__ hWh, const float* __restrict__ hbh,
           const float* __restrict__ lWi,
           const float* __restrict__ lWh, const float* __restrict__ lbh,
           const float* __restrict__ l2ow, const float* __restrict__ l2ob) {
    __shared__ __align__(16) float se[Bb * 1024];   // enc input, lives whole hstep
    __shared__ __align__(16) float sx[Bb * 1024];
    __shared__ __align__(16) float sy[Bb * 1024];
    __shared__ int s_vio[16];
    __shared__ float s_part[UPB][36];   // half1 partials

    int tid  = threadIdx.x;
    int lane = tid & 31;
    int wid  = tid >> 5;                // 0..15
    int half = wid >> 3;                // 0 | 1  (K-range)
    int jj   = wid & 7;                 // unit slot in block
    int j    = blockIdx.x * UPB + jj;
    bool act = (jj < UPB) && (j < Hh);
    unsigned gen = 0;
    int hc = 0, lc = 0;
    if (lane == 0) s_vio[wid] = 0;

    float bir=0, biz=0, bin_=0, bhr=0, bhz=0, bhn=0;
    float gbr=0, gbz=0, gbn=0, lbr=0, lbz=0, lbn=0, l2b=0;
    if (act) {
        bir = hbi[j]; biz = hbi[j + Hh]; bin_ = hbi[j + 2 * Hh];
        bhr = hbh[j]; bhz = hbh[j + Hh]; bhn  = hbh[j + 2 * Hh];
        gbr = g_bcomb[j]; gbz = g_bcomb[j + Hh]; gbn = g_bcomb[j + 2 * Hh];
        lbr = lbh[j]; lbz = lbh[j + Hh]; lbn = lbh[j + 2 * Hh];
        l2b = l2ob[j];
    }

    for (int t = 0; t < Tt; t++) {
        for (int hs = 0; hs < 2; hs++) {
            const float* ein; float* eout; long ebs, obs;
            if (hs == 0) { ein = g_enc + (size_t)t * Dd; ebs = (long)Tt * Dd;
                           eout = g_enc_cur;              obs = Dd; }
            else         { ein = g_enc_cur;               ebs = Dd;
                           eout = g_enc + (size_t)t * Dd; obs = (long)Tt * Dd; }

            // ---- P1: h-GRU + gil enc-part ----
            stage(se, ein, ebs);
            stage(sy, g_h + hc * Bb * Hh, Hh);
            __syncthreads();
            if (blockIdx.x == 0 && tid < 4) g_viol[tid] = 0;

            float si[12], shh[12], gpart[12];
            if (act) {
                sdot3x4h(hWi + (size_t)j * Dd, hWi + (size_t)(j + Hh) * Dd,
                         hWi + (size_t)(j + 2 * Hh) * Dd, se, half, si);
                sdot3x4h(hWh + (size_t)j * Hh, hWh + (size_t)(j + Hh) * Hh,
                         hWh + (size_t)(j + 2 * Hh) * Hh, sy, half, shh);
                sdot3x4h(lWi + (size_t)j * 2048, lWi + (size_t)(j + Hh) * 2048,
                         lWi + (size_t)(j + 2 * Hh) * 2048, se, half, gpart);
                if (half == 1 && lane == 0) {
#pragma unroll
                    for (int k = 0; k < 12; k++) {
                        s_part[jj][k]      = si[k];
                        s_part[jj][12 + k] = shh[k];
                        s_part[jj][24 + k] = gpart[k];
                    }
                }
            }
            __syncthreads();
            if (act && half == 0 && lane == 0) {
#pragma unroll
                for (int k = 0; k < 12; k++) {
                    si[k]    += s_part[jj][k];
                    shh[k]   += s_part[jj][12 + k];
                    gpart[k] += s_part[jj][24 + k];
                }
#pragma unroll
                for (int b = 0; b < Bb; b++) {
                    float r = sigm((si[b] + bir) + (shh[b] + bhr));
                    float z = sigm((si[4+b] + biz) + (shh[4+b] + bhz));
                    float n = tanhf((si[8+b] + bin_) + r * (shh[8+b] + bhn));
                    float hp = sy[b * 1024 + j];
                    g_h[(hc ^ 1) * Bb * Hh + b * Hh + j] = (1.f - z) * n + z * hp;
                }
            }
            gbar(nb, gen);
            hc ^= 1;

            // ---- P2: gil = gpart + W_comb@h_new + b_comb ; fused l-iter 0 ----
            stage(sy, g_h + hc * Bb * Hh, Hh);
            stage(sx, g_l + lc * Bb * Hh, Hh);
            if (lane == 0) s_vio[wid] = 0;
            __syncthreads();

            float gr[4], gz[4], gn2[4];
            {
                float s2[12], shl[12];
                if (act) {
                    sdot3x4h(g_wcomb + (size_t)j * Hh, g_wcomb + (size_t)(j + Hh) * Hh,
                             g_wcomb + (size_t)(j + 2 * Hh) * Hh, sy, half, s2);
                    sdot3x4h(lWh + (size_t)j * Hh, lWh + (size_t)(j + Hh) * Hh,
                             lWh + (size_t)(j + 2 * Hh) * Hh, sx, half, shl);
                    if (half == 1 && lane == 0) {
#pragma unroll
                        for (int k = 0; k < 12; k++) {
                            s_part[jj][k]      = s2[k];
                            s_part[jj][12 + k] = shl[k];
                        }
                    }
                }
                __syncthreads();
                if (act && half == 0 && lane == 0) {
                    bool vio = false;
#pragma unroll
                    for (int k = 0; k < 12; k++) {
                        s2[k]  += s_part[jj][k];
                        shl[k] += s_part[jj][12 + k];
                    }
#pragma unroll
                    for (int b = 0; b < Bb; b++) {
                        gr[b]  = gpart[b]     + s2[b]     + gbr;
                        gz[b]  = gpart[4 + b] + s2[4 + b] + gbz;
                        gn2[b] = gpart[8 + b] + s2[8 + b] + gbn;
                        float r = sigm(gr[b] + (shl[b] + lbr));
                        float z = sigm(gz[b] + (shl[4 + b] + lbz));
                        float n = tanhf(gn2[b] + r * (shl[8 + b] + lbn));
                        float old = sx[b * 1024 + j];
                        float nv = (1.f - z) * n + z * old;
                        if (fabsf(nv - old) > 1e-4f + 1e-5f * fabsf(old)) vio = true;
                        g_l[(lc ^ 1) * Bb * Hh + b * Hh + j] = nv;
                    }
                    if (vio) s_vio[wid] = 1;
                }
            }
            gbar_v(nb, gen, 0, s_vio);
            lc ^= 1;
            int conv = (ld_acq((const unsigned*)&g_viol[0]) == 0);

            // ---- remaining l-iterations ----
            for (int it = 1; it < 4 && !conv; it++) {
                stage(sx, g_l + lc * Bb * Hh, Hh);
                if (lane == 0) s_vio[wid] = 0;
                __syncthreads();
                float shl[12];
                if (act) {
                    sdot3x4h(lWh + (size_t)j * Hh, lWh + (size_t)(j + Hh) * Hh,
                             lWh + (size_t)(j + 2 * Hh) * Hh, sx, half, shl);
                    if (half == 1 && lane == 0) {
#pragma unroll
                        for (int k = 0; k < 12; k++) s_part[jj][k] = shl[k];
                    }
                }
                __syncthreads();
                if (act && half == 0 && lane == 0) {
                    bool vio = false;
#pragma unroll
                    for (int k = 0; k < 12; k++) shl[k] += s_part[jj][k];
#pragma unroll
                    for (int b = 0; b < Bb; b++) {
                        float r = sigm(gr[b] + (shl[b] + lbr));
                        float z = sigm(gz[b] + (shl[4 + b] + lbz));
                        float n = tanhf(gn2[b] + r * (shl[8 + b] + lbn));
                        float old = sx[b * 1024 + j];
                        float nv = (1.f - z) * n + z * old;
                        if (fabsf(nv - old) > 1e-4f + 1e-5f * fabsf(old)) vio = true;
                        g_l[(lc ^ 1) * Bb * Hh + b * Hh + j] = nv;
                    }
                    if (vio) s_vio[wid] = 1;
                }
                gbar_v(nb, gen, it, s_vio);
                lc ^= 1;
                conv = (ld_acq((const unsigned*)&g_viol[it]) == 0);
            }

            // ---- P5: enc = enc + l @ l2o^T + b (enc still in se) ----
            stage(sx, g_l + lc * Bb * Hh, Hh);
            __syncthreads();
            {
                float s[4];
                if (act) {
                    sdot1x4h(l2ow + (size_t)j * Hh, sx, half, s);
                    if (half == 1 && lane == 0) {
#pragma unroll
                        for (int k = 0; k < 4; k++) s_part[jj][k] = s[k];
                    }
                }
                __syncthreads();
                if (act && half == 0 && lane == 0) {
#pragma unroll
                    for (int b = 0; b < Bb; b++)
                        eout[(long)b * obs + j] =
                            se[b * 1024 + j] + s[b] + s_part[jj][b] + l2b;
                }
            }
            gbar(nb, gen);
        }
    }
}

// in-place layernorm of g_enc rows
__global__ void k_ln(const float* __restrict__ gam, const float* __restrict__ bet) {
    __shared__ float red[256];
    int row = blockIdx.x;
    float* x = g_enc + (size_t)row * Dd;
    int tid = threadIdx.x;
    float ls = 0.f;
    for (int i = tid; i < Dd; i += 256) ls += x[i];
    red[tid] = ls; __syncthreads();
    for (int s = 128; s > 0; s >>= 1) { if (tid < s) red[tid] += red[tid + s]; __syncthreads(); }
    float mu = red[0] / Dd;
    __syncthreads();
    float lv = 0.f;
    for (int i = tid; i < Dd; i += 256) { float dxx = x[i] - mu; lv += dxx * dxx; }
    red[tid] = lv; __syncthreads();
    for (int s = 128; s > 0; s >>= 1) { if (tid < s) red[tid] += red[tid + s]; __syncthreads(); }
    float rstd = rsqrtf(red[0] / Dd + 1e-5f);
    for (int i = tid; i < Dd; i += 256) x[i] = (x[i] - mu) * rstd * gam[i] + bet[i];
}

// ---------------- host ----------------
extern "C" void kernel_launch(void* const* d_in, const int* in_sizes, int n_in,
                              void* d_out, int out_size) {
    const int*   ids   = (const int*)d_in[0];
    const float* tok   = (const float*)d_in[1];
    const float* pos   = (const float*)d_in[2];
    const float* pers  = (const float*)d_in[3];
    const float* keys  = (const float*)d_in[4];
    const float* lvals = (const float*)d_in[5];
    const float* qw    = (const float*)d_in[6];
    const float* ipw   = (const float*)d_in[7];
    const float* ipb   = (const float*)d_in[8];
    const float* hWi   = (const float*)d_in[9];
    const float* hbi   = (const float*)d_in[10];
    const float* hWh   = (const float*)d_in[11];
    const float* hbh   = (const float*)d_in[12];
    const float* h2cw  = (const float*)d_in[13];
    const float* h2cb  = (const float*)d_in[14];
    const float* lWi   = (const float*)d_in[15];
    const float* lbi   = (const float*)d_in[16];
    const float* lWh   = (const float*)d_in[17];
    const float* lbh   = (const float*)d_in[18];
    const float* l2ow  = (const float*)d_in[19];
    const float* l2ob  = (const float*)d_in[20];
    const float* lng   = (const float*)d_in[21];
    const float* lnb   = (const float*)d_in[22];
    (void)in_sizes; (void)n_in;

    float* out = (float*)d_out;
    long LOGN = (long)Bb * Tt * Vv;
    long VALN = (long)Bb * Tt * TopK * VDim;
    long IDXN = (long)Bb * Tt * TopK;
    float* ov = nullptr; float* oi = nullptr;
    if ((long)out_size >= LOGN + VALN + IDXN) {
        ov = out + LOGN;
        oi = out + LOGN + VALN;
    }

    float *encp, *macp, *wcp, *bcp;
    cudaGetSymbolAddress((void**)&encp, g_enc);
    cudaGetSymbolAddress((void**)&macp, g_mac);
    cudaGetSymbolAddress((void**)&wcp,  g_wcomb);
    cudaGetSymbolAddress((void**)&bcp,  g_bcomb);

    int sm = 148;
    cudaDeviceGetAttribute(&sm, cudaDevAttrMultiProcessorCount, 0);
    int nb = sm;
    if (nb * UPB < Hh) nb = (Hh + UPB - 1) / UPB;
    if (nb > 256) nb = 256;

    k_init<<<32, 256>>>();

    { dim3 g(Tt, Bb); k_mac<<<g, 256>>>(ids, tok, pos, pers, keys, lvals, qw, ov, oi); }

    // enc0 = gelu(mac @ in_proj^T + b)
    k_gemm<<<dim3(Dd / 64, (Bb * Tt) / 64), 256>>>(macp, ipw, ipb, encp,
                                                   Bb * Tt, Dd, MACW, 1);

    // combined l-input weights: W_comb = lWi2 @ h2c, b_comb = lbi + lWi2 @ h2cb
    k_comb<<<dim3(Hh / 64, (3 * Hh) / 64), 256>>>(lWi, 2048, 1024, h2cw, wcp);
    k_vdot<<<384, 256>>>(lWi, 2048, 1024, h2cb, lbi, bcp);

    // the whole recurrence: one persistent kernel (512 threads, K-split warp pairs)
    k_seq<<<nb, 512>>>(nb, hWi, hbi, hWh, hbh, lWi, lWh, lbh, l2ow, l2ob);

    k_ln<<<Bb * Tt, 256>>>(lng, lnb);

    // logits = y @ tok_emb^T
    k_gemm<<<dim3(Vv / 64, (Bb * Tt) / 64), 256>>>(encp, tok, nullptr, out,
                                                   Bb * Tt, Vv, Dd, 0);
}

// round 16
// speedup vs baseline: 2.1137x; 2.1137x over previous
#include <cuda_runtime.h>
#include <cuda_bf16.h>
#include <math.h>

#define Bb   4
#define Tt   512
#define Dd   1024
#define Vv   32000
#define Pp   256
#define Ss   4096
#define KDim 64
#define VDim 64
#define TopK 4
#define Hh   1024
#define MACW 1536
#define UPB  7
#define SLOT 32

typedef unsigned long long u64;

// ---------------- device scratch ----------------
__device__ __align__(16) float g_mac[Bb * Tt * MACW];
__device__ __align__(16) float g_enc[Bb * Tt * Dd];
__device__ __align__(16) float g_enc_cur[Bb * Dd];
__device__ __align__(16) float g_h[2 * Bb * Hh];
__device__ __align__(16) float g_l[2 * Bb * Hh];
__device__ __align__(16) float g_wcomb[3 * Hh * Hh];   // lWi[:,1024:] @ h2c
__device__ __align__(16) float g_bcomb[3 * Hh];        // lbi + lWi2 @ h2cb
__device__ int g_viol[4];
__device__ unsigned g_slots[256 * SLOT];

// ---------------- helpers ----------------
__device__ __forceinline__ float warp_sum(float v) {
#pragma unroll
    for (int o = 16; o > 0; o >>= 1) v += __shfl_xor_sync(0xffffffffu, v, o);
    return v;
}
__device__ __forceinline__ float d4(float4 a, float4 b) {
    return a.x * b.x + a.y * b.y + a.z * b.z + a.w * b.w;
}
__device__ __forceinline__ float sigm(float x) { return 1.0f / (1.0f + expf(-x)); }
__device__ __forceinline__ float gelu_exact(float x) {
    return 0.5f * x * (1.0f + erff(x * 0.70710678118654752f));
}
__device__ __forceinline__ u64 f2fma(u64 a, u64 b, u64 c) {
    asm("fma.rn.f32x2 %0, %1, %2, %3;" : "=l"(c) : "l"(a), "l"(b), "l"(c));
    return c;
}
__device__ __forceinline__ float f2red(u64 a) {
    float lo, hi;
    asm("mov.b64 {%0, %1}, %2;" : "=f"(lo), "=f"(hi) : "l"(a));
    return lo + hi;
}
__device__ __forceinline__ u64 f2dup(float x) {
    u64 r;
    asm("mov.b64 %0, {%1, %1};" : "=l"(r) : "r"(__float_as_uint(x)));
    return r;
}
__device__ __forceinline__ float4 ldcv4(const float* p) {
    float4 v;
    asm volatile("ld.global.cv.v4.f32 {%0,%1,%2,%3}, [%4];"
                 : "=f"(v.x), "=f"(v.y), "=f"(v.z), "=f"(v.w) : "l"(p));
    return v;
}
__device__ __forceinline__ void st_rel(unsigned* p, unsigned v) {
    asm volatile("st.global.release.gpu.u32 [%0], %1;" :: "l"(p), "r"(v) : "memory");
}
__device__ __forceinline__ unsigned ld_acq(const unsigned* p) {
    unsigned v;
    asm volatile("ld.global.acquire.gpu.u32 %0, [%1];" : "=r"(v) : "l"(p) : "memory");
    return v;
}

// stage 4 batch-rows of 1024 floats into smem [4][1024] via .cv (blockDim==256)
__device__ __forceinline__ void stage(float* dst, const float* src, long bs) {
    int tid = threadIdx.x;
#pragma unroll
    for (int rr = 0; rr < 4; rr++) {
        int f = tid + rr * 256;
        int b = f >> 8, k = f & 255;
        ((float4*)dst)[f] = ldcv4(src + (long)b * bs + k * 4);
    }
}

// 6 weight rows x 4 batch vectors on the SAME x (single smem pass), f32x2
__device__ __forceinline__ void sdot6x4p(const float* __restrict__ w0,
                                         const float* __restrict__ w1,
                                         const float* __restrict__ w2,
                                         const float* __restrict__ w3,
                                         const float* __restrict__ w4,
                                         const float* __restrict__ w5,
                                         const float* xs, float out[24]) {
    const ulonglong2* W0 = (const ulonglong2*)w0;
    const ulonglong2* W1 = (const ulonglong2*)w1;
    const ulonglong2* W2 = (const ulonglong2*)w2;
    const ulonglong2* W3 = (const ulonglong2*)w3;
    const ulonglong2* W4 = (const ulonglong2*)w4;
    const ulonglong2* W5 = (const ulonglong2*)w5;
    const ulonglong2* X0 = (const ulonglong2*)xs;
    const ulonglong2* X1 = X0 + 256;
    const ulonglong2* X2 = X0 + 512;
    const ulonglong2* X3 = X0 + 768;
    int lane = threadIdx.x & 31;
    u64 acc[24] = {};
#pragma unroll
    for (int u = 0; u < 8; u++) {
        int i = lane + u * 32;
        ulonglong2 x0 = X0[i], x1 = X1[i], x2 = X2[i], x3 = X3[i];
        ulonglong2 a;
        a = W0[i];
        acc[0] = f2fma(a.x, x0.x, acc[0]); acc[0] = f2fma(a.y, x0.y, acc[0]);
        acc[1] = f2fma(a.x, x1.x, acc[1]); acc[1] = f2fma(a.y, x1.y, acc[1]);
        acc[2] = f2fma(a.x, x2.x, acc[2]); acc[2] = f2fma(a.y, x2.y, acc[2]);
        acc[3] = f2fma(a.x, x3.x, acc[3]); acc[3] = f2fma(a.y, x3.y, acc[3]);
        a = W1[i];
        acc[4] = f2fma(a.x, x0.x, acc[4]); acc[4] = f2fma(a.y, x0.y, acc[4]);
        acc[5] = f2fma(a.x, x1.x, acc[5]); acc[5] = f2fma(a.y, x1.y, acc[5]);
        acc[6] = f2fma(a.x, x2.x, acc[6]); acc[6] = f2fma(a.y, x2.y, acc[6]);
        acc[7] = f2fma(a.x, x3.x, acc[7]); acc[7] = f2fma(a.y, x3.y, acc[7]);
        a = W2[i];
        acc[8] = f2fma(a.x, x0.x, acc[8]); acc[8] = f2fma(a.y, x0.y, acc[8]);
        acc[9] = f2fma(a.x, x1.x, acc[9]); acc[9] = f2fma(a.y, x1.y, acc[9]);
        acc[10]= f2fma(a.x, x2.x, acc[10]);acc[10]= f2fma(a.y, x2.y, acc[10]);
        acc[11]= f2fma(a.x, x3.x, acc[11]);acc[11]= f2fma(a.y, x3.y, acc[11]);
        a = W3[i];
        acc[12]= f2fma(a.x, x0.x, acc[12]);acc[12]= f2fma(a.y, x0.y, acc[12]);
        acc[13]= f2fma(a.x, x1.x, acc[13]);acc[13]= f2fma(a.y, x1.y, acc[13]);
        acc[14]= f2fma(a.x, x2.x, acc[14]);acc[14]= f2fma(a.y, x2.y, acc[14]);
        acc[15]= f2fma(a.x, x3.x, acc[15]);acc[15]= f2fma(a.y, x3.y, acc[15]);
        a = W4[i];
        acc[16]= f2fma(a.x, x0.x, acc[16]);acc[16]= f2fma(a.y, x0.y, acc[16]);
        acc[17]= f2fma(a.x, x1.x, acc[17]);acc[17]= f2fma(a.y, x1.y, acc[17]);
        acc[18]= f2fma(a.x, x2.x, acc[18]);acc[18]= f2fma(a.y, x2.y, acc[18]);
        acc[19]= f2fma(a.x, x3.x, acc[19]);acc[19]= f2fma(a.y, x3.y, acc[19]);
        a = W5[i];
        acc[20]= f2fma(a.x, x0.x, acc[20]);acc[20]= f2fma(a.y, x0.y, acc[20]);
        acc[21]= f2fma(a.x, x1.x, acc[21]);acc[21]= f2fma(a.y, x1.y, acc[21]);
        acc[22]= f2fma(a.x, x2.x, acc[22]);acc[22]= f2fma(a.y, x2.y, acc[22]);
        acc[23]= f2fma(a.x, x3.x, acc[23]);acc[23]= f2fma(a.y, x3.y, acc[23]);
    }
#pragma unroll
    for (int k = 0; k < 24; k++) out[k] = warp_sum(f2red(acc[k]));
}

// 3 rows x xa  PLUS  3 rows x xb in one interleaved loop (double MLP)
__device__ __forceinline__ void sdot33x4p(const float* __restrict__ wa0,
                                          const float* __restrict__ wa1,
                                          const float* __restrict__ wa2,
                                          const float* xa,
                                          const float* __restrict__ wb0,
                                          const float* __restrict__ wb1,
                                          const float* __restrict__ wb2,
                                          const float* xb, float out[24]) {
    const ulonglong2* A0 = (const ulonglong2*)wa0;
    const ulonglong2* A1 = (const ulonglong2*)wa1;
    const ulonglong2* A2 = (const ulonglong2*)wa2;
    const ulonglong2* B0 = (const ulonglong2*)wb0;
    const ulonglong2* B1 = (const ulonglong2*)wb1;
    const ulonglong2* B2 = (const ulonglong2*)wb2;
    const ulonglong2* XA = (const ulonglong2*)xa;
    const ulonglong2* XB = (const ulonglong2*)xb;
    int lane = threadIdx.x & 31;
    u64 acc[24] = {};
#pragma unroll
    for (int u = 0; u < 8; u++) {
        int i = lane + u * 32;
        ulonglong2 x0 = XA[i], x1 = XA[256 + i], x2 = XA[512 + i], x3 = XA[768 + i];
        ulonglong2 y0 = XB[i], y1 = XB[256 + i], y2 = XB[512 + i], y3 = XB[768 + i];
        ulonglong2 a;
        a = A0[i];
        acc[0] = f2fma(a.x, x0.x, acc[0]); acc[0] = f2fma(a.y, x0.y, acc[0]);
        acc[1] = f2fma(a.x, x1.x, acc[1]); acc[1] = f2fma(a.y, x1.y, acc[1]);
        acc[2] = f2fma(a.x, x2.x, acc[2]); acc[2] = f2fma(a.y, x2.y, acc[2]);
        acc[3] = f2fma(a.x, x3.x, acc[3]); acc[3] = f2fma(a.y, x3.y, acc[3]);
        a = A1[i];
        acc[4] = f2fma(a.x, x0.x, acc[4]); acc[4] = f2fma(a.y, x0.y, acc[4]);
        acc[5] = f2fma(a.x, x1.x, acc[5]); acc[5] = f2fma(a.y, x1.y, acc[5]);
        acc[6] = f2fma(a.x, x2.x, acc[6]); acc[6] = f2fma(a.y, x2.y, acc[6]);
        acc[7] = f2fma(a.x, x3.x, acc[7]); acc[7] = f2fma(a.y, x3.y, acc[7]);
        a = A2[i];
        acc[8] = f2fma(a.x, x0.x, acc[8]); acc[8] = f2fma(a.y, x0.y, acc[8]);
        acc[9] = f2fma(a.x, x1.x, acc[9]); acc[9] = f2fma(a.y, x1.y, acc[9]);
        acc[10]= f2fma(a.x, x2.x, acc[10]);acc[10]= f2fma(a.y, x2.y, acc[10]);
        acc[11]= f2fma(a.x, x3.x, acc[11]);acc[11]= f2fma(a.y, x3.y, acc[11]);
        a = B0[i];
        acc[12]= f2fma(a.x, y0.x, acc[12]);acc[12]= f2fma(a.y, y0.y, acc[12]);
        acc[13]= f2fma(a.x, y1.x, acc[13]);acc[13]= f2fma(a.y, y1.y, acc[13]);
        acc[14]= f2fma(a.x, y2.x, acc[14]);acc[14]= f2fma(a.y, y2.y, acc[14]);
        acc[15]= f2fma(a.x, y3.x, acc[15]);acc[15]= f2fma(a.y, y3.y, acc[15]);
        a = B1[i];
        acc[16]= f2fma(a.x, y0.x, acc[16]);acc[16]= f2fma(a.y, y0.y, acc[16]);
        acc[17]= f2fma(a.x, y1.x, acc[17]);acc[17]= f2fma(a.y, y1.y, acc[17]);
        acc[18]= f2fma(a.x, y2.x, acc[18]);acc[18]= f2fma(a.y, y2.y, acc[18]);
        acc[19]= f2fma(a.x, y3.x, acc[19]);acc[19]= f2fma(a.y, y3.y, acc[19]);
        a = B2[i];
        acc[20]= f2fma(a.x, y0.x, acc[20]);acc[20]= f2fma(a.y, y0.y, acc[20]);
        acc[21]= f2fma(a.x, y1.x, acc[21]);acc[21]= f2fma(a.y, y1.y, acc[21]);
        acc[22]= f2fma(a.x, y2.x, acc[22]);acc[22]= f2fma(a.y, y2.y, acc[22]);
        acc[23]= f2fma(a.x, y3.x, acc[23]);acc[23]= f2fma(a.y, y3.y, acc[23]);
    }
#pragma unroll
    for (int k = 0; k < 24; k++) out[k] = warp_sum(f2red(acc[k]));
}

// 3 weight rows x 4 batch vectors, packed f32x2 -> out[row*4+b]
__device__ __forceinline__ void sdot3x4p(const float* __restrict__ w0,
                                         const float* __restrict__ w1,
                                         const float* __restrict__ w2,
                                         const float* xs, float out[12]) {
    const ulonglong2* W0 = (const ulonglong2*)w0;
    const ulonglong2* W1 = (const ulonglong2*)w1;
    const ulonglong2* W2 = (const ulonglong2*)w2;
    const ulonglong2* X0 = (const ulonglong2*)xs;
    const ulonglong2* X1 = X0 + 256;
    const ulonglong2* X2 = X0 + 512;
    const ulonglong2* X3 = X0 + 768;
    int lane = threadIdx.x & 31;
    u64 acc[12] = {};
#pragma unroll
    for (int u = 0; u < 8; u++) {
        int i = lane + u * 32;
        ulonglong2 a0 = W0[i], a1 = W1[i], a2 = W2[i];
        ulonglong2 x0 = X0[i], x1 = X1[i], x2 = X2[i], x3 = X3[i];
        acc[0] = f2fma(a0.x, x0.x, acc[0]); acc[0] = f2fma(a0.y, x0.y, acc[0]);
        acc[1] = f2fma(a0.x, x1.x, acc[1]); acc[1] = f2fma(a0.y, x1.y, acc[1]);
        acc[2] = f2fma(a0.x, x2.x, acc[2]); acc[2] = f2fma(a0.y, x2.y, acc[2]);
        acc[3] = f2fma(a0.x, x3.x, acc[3]); acc[3] = f2fma(a0.y, x3.y, acc[3]);
        acc[4] = f2fma(a1.x, x0.x, acc[4]); acc[4] = f2fma(a1.y, x0.y, acc[4]);
        acc[5] = f2fma(a1.x, x1.x, acc[5]); acc[5] = f2fma(a1.y, x1.y, acc[5]);
        acc[6] = f2fma(a1.x, x2.x, acc[6]); acc[6] = f2fma(a1.y, x2.y, acc[6]);
        acc[7] = f2fma(a1.x, x3.x, acc[7]); acc[7] = f2fma(a1.y, x3.y, acc[7]);
        acc[8] = f2fma(a2.x, x0.x, acc[8]); acc[8] = f2fma(a2.y, x0.y, acc[8]);
        acc[9] = f2fma(a2.x, x1.x, acc[9]); acc[9] = f2fma(a2.y, x1.y, acc[9]);
        acc[10]= f2fma(a2.x, x2.x, acc[10]);acc[10]= f2fma(a2.y, x2.y, acc[10]);
        acc[11]= f2fma(a2.x, x3.x, acc[11]);acc[11]= f2fma(a2.y, x3.y, acc[11]);
    }
#pragma unroll
    for (int k = 0; k < 12; k++) out[k] = warp_sum(f2red(acc[k]));
}

__device__ __forceinline__ void sdot1x4p(const float* __restrict__ w,
                                         const float* xs, float out[4]) {
    const ulonglong2* W  = (const ulonglong2*)w;
    const ulonglong2* X0 = (const ulonglong2*)xs;
    const ulonglong2* X1 = X0 + 256;
    const ulonglong2* X2 = X0 + 512;
    const ulonglong2* X3 = X0 + 768;
    int lane = threadIdx.x & 31;
    u64 acc[4] = {};
#pragma unroll
    for (int u = 0; u < 8; u++) {
        int i = lane + u * 32;
        ulonglong2 wv = W[i];
        ulonglong2 x0 = X0[i], x1 = X1[i], x2 = X2[i], x3 = X3[i];
        acc[0] = f2fma(wv.x, x0.x, acc[0]); acc[0] = f2fma(wv.y, x0.y, acc[0]);
        acc[1] = f2fma(wv.x, x1.x, acc[1]); acc[1] = f2fma(wv.y, x1.y, acc[1]);
        acc[2] = f2fma(wv.x, x2.x, acc[2]); acc[2] = f2fma(wv.y, x2.y, acc[2]);
        acc[3] = f2fma(wv.x, x3.x, acc[3]); acc[3] = f2fma(wv.y, x3.y, acc[3]);
    }
#pragma unroll
    for (int k = 0; k < 4; k++) out[k] = warp_sum(f2red(acc[k]));
}

// grid barrier (release/acquire, padded slots)
__device__ __forceinline__ void gbar(int nb, unsigned& gen) {
    gen++;
    __syncthreads();
    if (threadIdx.x == 0) st_rel(&g_slots[blockIdx.x * SLOT], gen);
    if ((int)threadIdx.x < nb)
        while (ld_acq(&g_slots[threadIdx.x * SLOT]) < gen) { }
    __syncthreads();
}
// barrier + per-block violation aggregation into g_viol[it]
__device__ __forceinline__ void gbar_v(int nb, unsigned& gen, int it, int* s_vio) {
    gen++;
    __syncthreads();
    if (threadIdx.x == 0) {
        int v = 0;
#pragma unroll
        for (int w = 0; w < 8; w++) v |= s_vio[w];
        if (v) atomicOr(&g_viol[it], 1);
        st_rel(&g_slots[blockIdx.x * SLOT], gen);
    }
    if ((int)threadIdx.x < nb && threadIdx.x != 0)
        while (ld_acq(&g_slots[threadIdx.x * SLOT]) < gen) { }
    if (threadIdx.x == 0)
        while (ld_acq(&g_slots[0]) < gen) { }
    __syncthreads();
}

// ---------------- kernels ----------------
__global__ void k_init() {
    int i = blockIdx.x * blockDim.x + threadIdx.x;
    if (i < 256 * SLOT) g_slots[i] = 0;
    if (i < 4) g_viol[i] = 0;
    for (int k = i; k < 2 * Bb * Hh; k += gridDim.x * blockDim.x) {
        g_h[k] = 0.f; g_l[k] = 0.f;
    }
}

__global__ void k_mac(const int* __restrict__ ids, const float* __restrict__ tok,
                      const float* __restrict__ pos, const float* __restrict__ pers,
                      const float* __restrict__ keys, const float* __restrict__ lvals,
                      const float* __restrict__ qw,
                      float* __restrict__ out_vals, float* __restrict__ out_idx) {
    __shared__ __align__(16) float sx[Dd];
    __shared__ __align__(16) float sq[KDim];
    __shared__ float ssim[Ss];
    __shared__ float rv[256];
    __shared__ int   ri[256];
    __shared__ int   s_top[TopK];

    int t = blockIdx.x, b = blockIdx.y;
    int tid = threadIdx.x;
    long row = (long)b * Tt + t;
    float* macrow = g_mac + row * MACW;

    int id = ids[b * Tt + t];
    for (int d = tid; d < Dd; d += 256) {
        float v = tok[(size_t)id * Dd + d] + pos[(size_t)t * Dd + d];
        sx[d] = v;
        macrow[d] = v;
    }
    for (int p = tid; p < Pp; p += 256) macrow[Dd + p] = pers[p];
    __syncthreads();

    int wid = tid >> 5, lane = tid & 31;
    for (int o = wid; o < KDim; o += 8) {
        const float4* W = (const float4*)(qw + (size_t)o * Dd);
        const float4* X = (const float4*)sx;
        float s = 0.f;
        for (int i = lane; i < Dd / 4; i += 32) s += d4(W[i], X[i]);
        s = warp_sum(s);
        if (lane == 0) sq[o] = s;
    }
    __syncthreads();

    for (int i = tid; i < Ss; i += 256) {
        const float4* Kr = (const float4*)(keys + (size_t)i * KDim);
        const float4* Q  = (const float4*)sq;
        float s = 0.f;
#pragma unroll
        for (int q = 0; q < 16; q++) s += d4(Kr[q], Q[q]);
        ssim[i] = s;
    }
    __syncthreads();

    for (int kk = 0; kk < TopK; kk++) {
        float bv = -1e30f; int bi2 = 0x7fffffff;
        for (int i = tid; i < Ss; i += 256) {
            float v = ssim[i];
            if (v > bv || (v == bv && i < bi2)) { bv = v; bi2 = i; }
        }
        rv[tid] = bv; ri[tid] = bi2;
        __syncthreads();
        for (int s = 128; s > 0; s >>= 1) {
            if (tid < s) {
                if (rv[tid + s] > rv[tid] ||
                    (rv[tid + s] == rv[tid] && ri[tid + s] < ri[tid])) {
                    rv[tid] = rv[tid + s]; ri[tid] = ri[tid + s];
                }
            }
            __syncthreads();
        }
        if (tid == 0) { s_top[kk] = ri[0]; ssim[ri[0]] = -1e38f; }
        __syncthreads();
    }

    for (int kk = 0; kk < TopK; kk++) {
        int ix = s_top[kk];
        for (int v = tid; v < VDim; v += 256) {
            float val = lvals[(size_t)ix * VDim + v];
            macrow[Dd + Pp + kk * VDim + v] = val;
            if (out_vals) out_vals[(row * TopK + kk) * VDim + v] = val;
        }
        if (tid == 0 && out_idx) out_idx[row * TopK + kk] = (float)ix;
    }
}

// C[M,N] = A[M,K] * B[N,K]^T ; epi=1 -> bias + exact gelu  (f32x2 inner)
__global__ void k_gemm(const float* __restrict__ A, const float* __restrict__ Bm,
                       const float* __restrict__ bias, float* __restrict__ C,
                       int M, int N, int Kd, int epi) {
    __shared__ __align__(16) float As[16][68];
    __shared__ __align__(16) float Bs[16][68];
    int tid = threadIdx.x;
    int tx = tid & 15, ty = tid >> 4;
    int q = tid & 3,  r  = tid >> 2;
    int m0 = blockIdx.y * 64, n0 = blockIdx.x * 64;
    u64 acc2[4][2] = {};
    for (int kt = 0; kt < Kd; kt += 16) {
        float4 av = *(const float4*)&A[(size_t)(m0 + r) * Kd + kt + q * 4];
        float4 bv = *(const float4*)&Bm[(size_t)(n0 + r) * Kd + kt + q * 4];
        As[q*4+0][r]=av.x; As[q*4+1][r]=av.y; As[q*4+2][r]=av.z; As[q*4+3][r]=av.w;
        Bs[q*4+0][r]=bv.x; Bs[q*4+1][r]=bv.y; Bs[q*4+2][r]=bv.z; Bs[q*4+3][r]=bv.w;
        __syncthreads();
#pragma unroll
        for (int kk = 0; kk < 16; kk++) {
            float4 a = *(const float4*)&As[kk][ty * 4];
            ulonglong2 bp = *(const ulonglong2*)&Bs[kk][tx * 4];
            u64 a0 = f2dup(a.x), a1 = f2dup(a.y), a2 = f2dup(a.z), a3 = f2dup(a.w);
            acc2[0][0] = f2fma(a0, bp.x, acc2[0][0]); acc2[0][1] = f2fma(a0, bp.y, acc2[0][1]);
            acc2[1][0] = f2fma(a1, bp.x, acc2[1][0]); acc2[1][1] = f2fma(a1, bp.y, acc2[1][1]);
            acc2[2][0] = f2fma(a2, bp.x, acc2[2][0]); acc2[2][1] = f2fma(a2, bp.y, acc2[2][1]);
            acc2[3][0] = f2fma(a3, bp.x, acc2[3][0]); acc2[3][1] = f2fma(a3, bp.y, acc2[3][1]);
        }
        __syncthreads();
    }
#pragma unroll
    for (int i = 0; i < 4; i++) {
        int m = m0 + ty * 4 + i;
#pragma unroll
        for (int jh = 0; jh < 2; jh++) {
            float lo, hi;
            asm("mov.b64 {%0, %1}, %2;" : "=f"(lo), "=f"(hi) : "l"(acc2[i][jh]));
            int n = n0 + tx * 4 + jh * 2;
            float v0 = lo, v1 = hi;
            if (epi) {
                v0 = gelu_exact(v0 + bias[n]);
                v1 = gelu_exact(v1 + bias[n + 1]);
            }
            C[(size_t)m * N + n]     = v0;
            C[(size_t)m * N + n + 1] = v1;
        }
    }
}

// C[3072][1024] = A(rows stride rstride, col offset coff) @ Bm[1024,1024]
__global__ void k_comb(const float* __restrict__ A, long rstride, long coff,
                       const float* __restrict__ Bm, float* __restrict__ C) {
    __shared__ __align__(16) float As[16][68];
    __shared__ __align__(16) float Bs[16][68];
    int tid = threadIdx.x;
    int tx = tid & 15, ty = tid >> 4;
    int q = tid & 3,  r  = tid >> 2;
    int rr = tid >> 4, cc = tid & 15;
    int n0 = blockIdx.x * 64, m0 = blockIdx.y * 64;
    float acc[4][4] = {};
    for (int d0 = 0; d0 < Hh; d0 += 16) {
        float4 av = *(const float4*)&A[(size_t)(m0 + r) * rstride + coff + d0 + q * 4];
        As[q*4+0][r]=av.x; As[q*4+1][r]=av.y; As[q*4+2][r]=av.z; As[q*4+3][r]=av.w;
        float4 bv = *(const float4*)&Bm[(size_t)(d0 + rr) * Hh + n0 + cc * 4];
        *(float4*)&Bs[rr][cc * 4] = bv;
        __syncthreads();
#pragma unroll
        for (int kk = 0; kk < 16; kk++) {
            float4 a = *(const float4*)&As[kk][ty * 4];
            float4 b = *(const float4*)&Bs[kk][tx * 4];
            acc[0][0]+=a.x*b.x; acc[0][1]+=a.x*b.y; acc[0][2]+=a.x*b.z; acc[0][3]+=a.x*b.w;
            acc[1][0]+=a.y*b.x; acc[1][1]+=a.y*b.y; acc[1][2]+=a.y*b.z; acc[1][3]+=a.y*b.w;
            acc[2][0]+=a.z*b.x; acc[2][1]+=a.z*b.y; acc[2][2]+=a.z*b.z; acc[2][3]+=a.z*b.w;
            acc[3][0]+=a.w*b.x; acc[3][1]+=a.w*b.y; acc[3][2]+=a.w*b.z; acc[3][3]+=a.w*b.w;
        }
        __syncthreads();
    }
#pragma unroll
    for (int i = 0; i < 4; i++)
#pragma unroll
        for (int j = 0; j < 4; j++)
            C[(size_t)(m0 + ty * 4 + i) * Hh + n0 + tx * 4 + j] = acc[i][j];
}

// out[r] = addb[r] + dot(W[r*rstride+coff .. +1024], v)
__global__ void k_vdot(const float* __restrict__ W, long rstride, long coff,
                       const float* __restrict__ v, const float* __restrict__ addb,
                       float* __restrict__ out) {
    int r = (blockIdx.x * blockDim.x + threadIdx.x) >> 5;
    if (r >= 3 * Hh) return;
    const float4* Wr = (const float4*)(W + (size_t)r * rstride + coff);
    const float4* X  = (const float4*)v;
    int lane = threadIdx.x & 31;
    float s = 0.f;
    for (int i = lane; i < 256; i += 32) s += d4(Wr[i], X[i]);
    s = warp_sum(s);
    if (lane == 0) out[r] = (addb ? addb[r] : 0.f) + s;
}

// ---- persistent recurrence: 256 threads, warp per hidden unit, fused dots ----
__global__ __launch_bounds__(256, 1)
void k_seq(int nb,
           const float* __restrict__ hWi, const float* __restrict__ hbi,
           const float* __restrict__ hWh, const float* __restrict__ hbh,
           const float* __restrict__ lWi,
           const float* __restrict__ lWh, const float* __restrict__ lbh,
           const float* __restrict__ l2ow, const float* __restrict__ l2ob) {
    __shared__ __align__(16) float se[Bb * 1024];   // enc input, lives whole hstep
    __shared__ __align__(16) float sx[Bb * 1024];
    __shared__ __align__(16) float sy[Bb * 1024];
    __shared__ int s_vio[8];

    int tid  = threadIdx.x;
    int lane = tid & 31;
    int wid  = tid >> 5;                  // 0..7
    int j    = blockIdx.x * UPB + wid;    // hidden unit (warp 7 inactive)
    bool act = (wid < UPB) && (j < Hh);
    unsigned gen = 0;
    int hc = 0, lc = 0;
    if (lane == 0) s_vio[wid] = 0;

    float bir=0, biz=0, bin_=0, bhr=0, bhz=0, bhn=0;
    float gbr=0, gbz=0, gbn=0, lbr=0, lbz=0, lbn=0, l2b=0;
    if (act) {
        bir = hbi[j]; biz = hbi[j + Hh]; bin_ = hbi[j + 2 * Hh];
        bhr = hbh[j]; bhz = hbh[j + Hh]; bhn  = hbh[j + 2 * Hh];
        gbr = g_bcomb[j]; gbz = g_bcomb[j + Hh]; gbn = g_bcomb[j + 2 * Hh];
        lbr = lbh[j]; lbz = lbh[j + Hh]; lbn = lbh[j + 2 * Hh];
        l2b = l2ob[j];
    }

    for (int t = 0; t < Tt; t++) {
        for (int hs = 0; hs < 2; hs++) {
            const float* ein; float* eout; long ebs, obs;
            if (hs == 0) { ein = g_enc + (size_t)t * Dd; ebs = (long)Tt * Dd;
                           eout = g_enc_cur;              obs = Dd; }
            else         { ein = g_enc_cur;               ebs = Dd;
                           eout = g_enc + (size_t)t * Dd; obs = (long)Tt * Dd; }

            // ---- P1: h-GRU + gil enc-part (fused: one pass over se) ----
            stage(se, ein, ebs);
            stage(sy, g_h + hc * Bb * Hh, Hh);
            __syncthreads();
            if (blockIdx.x == 0 && tid < 4) g_viol[tid] = 0;

            float gpart[12];
            if (act) {
                float sg[24], shh[12];
                sdot6x4p(hWi + (size_t)j * Dd, hWi + (size_t)(j + Hh) * Dd,
                         hWi + (size_t)(j + 2 * Hh) * Dd,
                         lWi + (size_t)j * 2048, lWi + (size_t)(j + Hh) * 2048,
                         lWi + (size_t)(j + 2 * Hh) * 2048, se, sg);
                sdot3x4p(hWh + (size_t)j * Hh, hWh + (size_t)(j + Hh) * Hh,
                         hWh + (size_t)(j + 2 * Hh) * Hh, sy, shh);
#pragma unroll
                for (int k = 0; k < 12; k++) gpart[k] = sg[12 + k];
                if (lane == 0) {
#pragma unroll
                    for (int b = 0; b < Bb; b++) {
                        float r = sigm((sg[b] + bir) + (shh[b] + bhr));
                        float z = sigm((sg[4+b] + biz) + (shh[4+b] + bhz));
                        float n = tanhf((sg[8+b] + bin_) + r * (shh[8+b] + bhn));
                        float hp = sy[b * 1024 + j];
                        g_h[(hc ^ 1) * Bb * Hh + b * Hh + j] = (1.f - z) * n + z * hp;
                    }
                }
            }
            gbar(nb, gen);
            hc ^= 1;

            // ---- P2: gil + fused l-iter 0 (one interleaved pass over sy & sx) ----
            stage(sy, g_h + hc * Bb * Hh, Hh);
            stage(sx, g_l + lc * Bb * Hh, Hh);
            if (lane == 0) s_vio[wid] = 0;
            __syncthreads();

            float gr[4], gz[4], gn2[4];
            if (act) {
                float d2[24];
                sdot33x4p(g_wcomb + (size_t)j * Hh, g_wcomb + (size_t)(j + Hh) * Hh,
                          g_wcomb + (size_t)(j + 2 * Hh) * Hh, sy,
                          lWh + (size_t)j * Hh, lWh + (size_t)(j + Hh) * Hh,
                          lWh + (size_t)(j + 2 * Hh) * Hh, sx, d2);
                if (lane == 0) {
                    bool vio = false;
#pragma unroll
                    for (int b = 0; b < Bb; b++) {
                        gr[b]  = gpart[b]     + d2[b]     + gbr;
                        gz[b]  = gpart[4 + b] + d2[4 + b] + gbz;
                        gn2[b] = gpart[8 + b] + d2[8 + b] + gbn;
                        float r = sigm(gr[b] + (d2[12 + b] + lbr));
                        float z = sigm(gz[b] + (d2[16 + b] + lbz));
                        float n = tanhf(gn2[b] + r * (d2[20 + b] + lbn));
                        float old = sx[b * 1024 + j];
                        float nv = (1.f - z) * n + z * old;
                        if (fabsf(nv - old) > 1e-4f + 1e-5f * fabsf(old)) vio = true;
                        g_l[(lc ^ 1) * Bb * Hh + b * Hh + j] = nv;
                    }
                    if (vio) s_vio[wid] = 1;
                }
            }
            gbar_v(nb, gen, 0, s_vio);
            lc ^= 1;
            int conv = (ld_acq((const unsigned*)&g_viol[0]) == 0);

            // ---- remaining l-iterations ----
            for (int it = 1; it < 4 && !conv; it++) {
                stage(sx, g_l + lc * Bb * Hh, Hh);
                if (lane == 0) s_vio[wid] = 0;
                __syncthreads();
                if (act) {
                    float shl[12];
                    sdot3x4p(lWh + (size_t)j * Hh, lWh + (size_t)(j + Hh) * Hh,
                             lWh + (size_t)(j + 2 * Hh) * Hh, sx, shl);
                    if (lane == 0) {
                        bool vio = false;
#pragma unroll
                        for (int b = 0; b < Bb; b++) {
                            float r = sigm(gr[b] + (shl[b] + lbr));
                            float z = sigm(gz[b] + (shl[4 + b] + lbz));
                            float n = tanhf(gn2[b] + r * (shl[8 + b] + lbn));
                            float old = sx[b * 1024 + j];
                            float nv = (1.f - z) * n + z * old;
                            if (fabsf(nv - old) > 1e-4f + 1e-5f * fabsf(old)) vio = true;
                            g_l[(lc ^ 1) * Bb * Hh + b * Hh + j] = nv;
                        }
                        if (vio) s_vio[wid] = 1;
                    }
                }
                gbar_v(nb, gen, it, s_vio);
                lc ^= 1;
                conv = (ld_acq((const unsigned*)&g_viol[it]) == 0);
            }

            // ---- P5: enc = enc + l @ l2o^T + b (enc still in se) ----
            stage(sx, g_l + lc * Bb * Hh, Hh);
            __syncthreads();
            if (act) {
                float s[4];
                sdot1x4p(l2ow + (size_t)j * Hh, sx, s);
                if (lane == 0)
#pragma unroll
                    for (int b = 0; b < Bb; b++)
                        eout[(long)b * obs + j] = se[b * 1024 + j] + s[b] + l2b;
            }
            gbar(nb, gen);
        }
    }
}

// in-place layernorm of g_enc rows
__global__ void k_ln(const float* __restrict__ gam, const float* __restrict__ bet) {
    __shared__ float red[256];
    int row = blockIdx.x;
    float* x = g_enc + (size_t)row * Dd;
    int tid = threadIdx.x;
    float ls = 0.f;
    for (int i = tid; i < Dd; i += 256) ls += x[i];
    red[tid] = ls; __syncthreads();
    for (int s = 128; s > 0; s >>= 1) { if (tid < s) red[tid] += red[tid + s]; __syncthreads(); }
    float mu = red[0] / Dd;
    __syncthreads();
    float lv = 0.f;
    for (int i = tid; i < Dd; i += 256) { float dxx = x[i] - mu; lv += dxx * dxx; }
    red[tid] = lv; __syncthreads();
    for (int s = 128; s > 0; s >>= 1) { if (tid < s) red[tid] += red[tid + s]; __syncthreads(); }
    float rstd = rsqrtf(red[0] / Dd + 1e-5f);
    for (int i = tid; i < Dd; i += 256) x[i] = (x[i] - mu) * rstd * gam[i] + bet[i];
}

// ---------------- host ----------------
extern "C" void kernel_launch(void* const* d_in, const int* in_sizes, int n_in,
                              void* d_out, int out_size) {
    const int*   ids   = (const int*)d_in[0];
    const float* tok   = (const float*)d_in[1];
    const float* pos   = (const float*)d_in[2];
    const float* pers  = (const float*)d_in[3];
    const float* keys  = (const float*)d_in[4];
    const float* lvals = (const float*)d_in[5];
    const float* qw    = (const float*)d_in[6];
    const float* ipw   = (const float*)d_in[7];
    const float* ipb   = (const float*)d_in[8];
    const float* hWi   = (const float*)d_in[9];
    const float* hbi   = (const float*)d_in[10];
    const float* hWh   = (const float*)d_in[11];
    const float* hbh   = (const float*)d_in[12];
    const float* h2cw  = (const float*)d_in[13];
    const float* h2cb  = (const float*)d_in[14];
    const float* lWi   = (const float*)d_in[15];
    const float* lbi   = (const float*)d_in[16];
    const float* lWh   = (const float*)d_in[17];
    const float* lbh   = (const float*)d_in[18];
    const float* l2ow  = (const float*)d_in[19];
    const float* l2ob  = (const float*)d_in[20];
    const float* lng   = (const float*)d_in[21];
    const float* lnb   = (const float*)d_in[22];
    (void)in_sizes; (void)n_in;

    float* out = (float*)d_out;
    long LOGN = (long)Bb * Tt * Vv;
    long VALN = (long)Bb * Tt * TopK * VDim;
    long IDXN = (long)Bb * Tt * TopK;
    float* ov = nullptr; float* oi = nullptr;
    if ((long)out_size >= LOGN + VALN + IDXN) {
        ov = out + LOGN;
        oi = out + LOGN + VALN;
    }

    float *encp, *macp, *wcp, *bcp;
    cudaGetSymbolAddress((void**)&encp, g_enc);
    cudaGetSymbolAddress((void**)&macp, g_mac);
    cudaGetSymbolAddress((void**)&wcp,  g_wcomb);
    cudaGetSymbolAddress((void**)&bcp,  g_bcomb);

    int sm = 148;
    cudaDeviceGetAttribute(&sm, cudaDevAttrMultiProcessorCount, 0);
    int nb = sm;
    if (nb * UPB < Hh) nb = (Hh + UPB - 1) / UPB;
    if (nb > 256) nb = 256;

    k_init<<<32, 256>>>();

    { dim3 g(Tt, Bb); k_mac<<<g, 256>>>(ids, tok, pos, pers, keys, lvals, qw, ov, oi); }

    // enc0 = gelu(mac @ in_proj^T + b)
    k_gemm<<<dim3(Dd / 64, (Bb * Tt) / 64), 256>>>(macp, ipw, ipb, encp,
                                                   Bb * Tt, Dd, MACW, 1);

    // combined l-input weights: W_comb = lWi2 @ h2c, b_comb = lbi + lWi2 @ h2cb
    k_comb<<<dim3(Hh / 64, (3 * Hh) / 64), 256>>>(lWi, 2048, 1024, h2cw, wcp);
    k_vdot<<<384, 256>>>(lWi, 2048, 1024, h2cb, lbi, bcp);

    // the whole recurrence: one persistent kernel (256 threads, warp per unit)
    k_seq<<<nb, 256>>>(nb, hWi, hbi, hWh, hbh, lWi, lWh, lbh, l2ow, l2ob);

    k_ln<<<Bb * Tt, 256>>>(lng, lnb);

    // logits = y @ tok_emb^T
    k_gemm<<<dim3(Vv / 64, (Bb * Tt) / 64), 256>>>(encp, tok, nullptr, out,
                                                   Bb * Tt, Vv, Dd, 0);
}

// round 17
// speedup vs baseline: 2.1879x; 1.0351x over previous
#include <cuda_runtime.h>
#include <cuda_bf16.h>
#include <math.h>

#define Bb   4
#define Tt   512
#define Dd   1024
#define Vv   32000
#define Pp   256
#define Ss   4096
#define KDim 64
#define VDim 64
#define TopK 4
#define Hh   1024
#define MACW 1536
#define UPB  7
#define SLOT 32

typedef unsigned long long u64;

// ---------------- device scratch ----------------
__device__ __align__(16) float g_mac[Bb * Tt * MACW];
__device__ __align__(16) float g_enc[Bb * Tt * Dd];
__device__ __align__(16) float g_enc_cur[Bb * Dd];
__device__ __align__(16) float g_h[2 * Bb * Hh];
__device__ __align__(16) float g_l[2 * Bb * Hh];
__device__ __align__(16) float g_wcomb[3 * Hh * Hh];   // lWi[:,1024:] @ h2c
__device__ __align__(16) float g_bcomb[3 * Hh];        // lbi + lWi2 @ h2cb
__device__ unsigned g_slots[2][256 * SLOT];            // ping-pong arrival slots

// ---------------- helpers ----------------
__device__ __forceinline__ float warp_sum(float v) {
#pragma unroll
    for (int o = 16; o > 0; o >>= 1) v += __shfl_xor_sync(0xffffffffu, v, o);
    return v;
}
__device__ __forceinline__ float d4(float4 a, float4 b) {
    return a.x * b.x + a.y * b.y + a.z * b.z + a.w * b.w;
}
__device__ __forceinline__ float sigm(float x) { return 1.0f / (1.0f + expf(-x)); }
__device__ __forceinline__ float gelu_exact(float x) {
    return 0.5f * x * (1.0f + erff(x * 0.70710678118654752f));
}
__device__ __forceinline__ u64 f2fma(u64 a, u64 b, u64 c) {
    asm("fma.rn.f32x2 %0, %1, %2, %3;" : "=l"(c) : "l"(a), "l"(b), "l"(c));
    return c;
}
__device__ __forceinline__ float f2red(u64 a) {
    float lo, hi;
    asm("mov.b64 {%0, %1}, %2;" : "=f"(lo), "=f"(hi) : "l"(a));
    return lo + hi;
}
__device__ __forceinline__ u64 f2dup(float x) {
    u64 r;
    asm("mov.b64 %0, {%1, %1};" : "=l"(r) : "r"(__float_as_uint(x)));
    return r;
}
__device__ __forceinline__ float4 ldcv4(const float* p) {
    float4 v;
    asm volatile("ld.global.cv.v4.f32 {%0,%1,%2,%3}, [%4];"
                 : "=f"(v.x), "=f"(v.y), "=f"(v.z), "=f"(v.w) : "l"(p));
    return v;
}
__device__ __forceinline__ void st_rel(unsigned* p, unsigned v) {
    asm volatile("st.global.release.gpu.u32 [%0], %1;" :: "l"(p), "r"(v) : "memory");
}
__device__ __forceinline__ unsigned ld_acq(const unsigned* p) {
    unsigned v;
    asm volatile("ld.global.acquire.gpu.u32 %0, [%1];" : "=r"(v) : "l"(p) : "memory");
    return v;
}

// stage 4 batch-rows of 1024 floats into smem [4][1024] via .cv (blockDim==256)
__device__ __forceinline__ void stage(float* dst, const float* src, long bs) {
    int tid = threadIdx.x;
#pragma unroll
    for (int rr = 0; rr < 4; rr++) {
        int f = tid + rr * 256;
        int b = f >> 8, k = f & 255;
        ((float4*)dst)[f] = ldcv4(src + (long)b * bs + k * 4);
    }
}

// 6 weight rows x 4 batch vectors on the SAME x (single smem pass), f32x2
__device__ __forceinline__ void sdot6x4p(const float* __restrict__ w0,
                                         const float* __restrict__ w1,
                                         const float* __restrict__ w2,
                                         const float* __restrict__ w3,
                                         const float* __restrict__ w4,
                                         const float* __restrict__ w5,
                                         const float* xs, float out[24]) {
    const ulonglong2* W0 = (const ulonglong2*)w0;
    const ulonglong2* W1 = (const ulonglong2*)w1;
    const ulonglong2* W2 = (const ulonglong2*)w2;
    const ulonglong2* W3 = (const ulonglong2*)w3;
    const ulonglong2* W4 = (const ulonglong2*)w4;
    const ulonglong2* W5 = (const ulonglong2*)w5;
    const ulonglong2* X0 = (const ulonglong2*)xs;
    const ulonglong2* X1 = X0 + 256;
    const ulonglong2* X2 = X0 + 512;
    const ulonglong2* X3 = X0 + 768;
    int lane = threadIdx.x & 31;
    u64 acc[24] = {};
#pragma unroll
    for (int u = 0; u < 8; u++) {
        int i = lane + u * 32;
        ulonglong2 x0 = X0[i], x1 = X1[i], x2 = X2[i], x3 = X3[i];
        ulonglong2 a;
        a = W0[i];
        acc[0] = f2fma(a.x, x0.x, acc[0]); acc[0] = f2fma(a.y, x0.y, acc[0]);
        acc[1] = f2fma(a.x, x1.x, acc[1]); acc[1] = f2fma(a.y, x1.y, acc[1]);
        acc[2] = f2fma(a.x, x2.x, acc[2]); acc[2] = f2fma(a.y, x2.y, acc[2]);
        acc[3] = f2fma(a.x, x3.x, acc[3]); acc[3] = f2fma(a.y, x3.y, acc[3]);
        a = W1[i];
        acc[4] = f2fma(a.x, x0.x, acc[4]); acc[4] = f2fma(a.y, x0.y, acc[4]);
        acc[5] = f2fma(a.x, x1.x, acc[5]); acc[5] = f2fma(a.y, x1.y, acc[5]);
        acc[6] = f2fma(a.x, x2.x, acc[6]); acc[6] = f2fma(a.y, x2.y, acc[6]);
        acc[7] = f2fma(a.x, x3.x, acc[7]); acc[7] = f2fma(a.y, x3.y, acc[7]);
        a = W2[i];
        acc[8] = f2fma(a.x, x0.x, acc[8]); acc[8] = f2fma(a.y, x0.y, acc[8]);
        acc[9] = f2fma(a.x, x1.x, acc[9]); acc[9] = f2fma(a.y, x1.y, acc[9]);
        acc[10]= f2fma(a.x, x2.x, acc[10]);acc[10]= f2fma(a.y, x2.y, acc[10]);
        acc[11]= f2fma(a.x, x3.x, acc[11]);acc[11]= f2fma(a.y, x3.y, acc[11]);
        a = W3[i];
        acc[12]= f2fma(a.x, x0.x, acc[12]);acc[12]= f2fma(a.y, x0.y, acc[12]);
        acc[13]= f2fma(a.x, x1.x, acc[13]);acc[13]= f2fma(a.y, x1.y, acc[13]);
        acc[14]= f2fma(a.x, x2.x, acc[14]);acc[14]= f2fma(a.y, x2.y, acc[14]);
        acc[15]= f2fma(a.x, x3.x, acc[15]);acc[15]= f2fma(a.y, x3.y, acc[15]);
        a = W4[i];
        acc[16]= f2fma(a.x, x0.x, acc[16]);acc[16]= f2fma(a.y, x0.y, acc[16]);
        acc[17]= f2fma(a.x, x1.x, acc[17]);acc[17]= f2fma(a.y, x1.y, acc[17]);
        acc[18]= f2fma(a.x, x2.x, acc[18]);acc[18]= f2fma(a.y, x2.y, acc[18]);
        acc[19]= f2fma(a.x, x3.x, acc[19]);acc[19]= f2fma(a.y, x3.y, acc[19]);
        a = W5[i];
        acc[20]= f2fma(a.x, x0.x, acc[20]);acc[20]= f2fma(a.y, x0.y, acc[20]);
        acc[21]= f2fma(a.x, x1.x, acc[21]);acc[21]= f2fma(a.y, x1.y, acc[21]);
        acc[22]= f2fma(a.x, x2.x, acc[22]);acc[22]= f2fma(a.y, x2.y, acc[22]);
        acc[23]= f2fma(a.x, x3.x, acc[23]);acc[23]= f2fma(a.y, x3.y, acc[23]);
    }
#pragma unroll
    for (int k = 0; k < 24; k++) out[k] = warp_sum(f2red(acc[k]));
}

// 3 rows x xa  PLUS  3 rows x xb in one interleaved loop (double MLP)
__device__ __forceinline__ void sdot33x4p(const float* __restrict__ wa0,
                                          const float* __restrict__ wa1,
                                          const float* __restrict__ wa2,
                                          const float* xa,
                                          const float* __restrict__ wb0,
                                          const float* __restrict__ wb1,
                                          const float* __restrict__ wb2,
                                          const float* xb, float out[24]) {
    const ulonglong2* A0 = (const ulonglong2*)wa0;
    const ulonglong2* A1 = (const ulonglong2*)wa1;
    const ulonglong2* A2 = (const ulonglong2*)wa2;
    const ulonglong2* B0 = (const ulonglong2*)wb0;
    const ulonglong2* B1 = (const ulonglong2*)wb1;
    const ulonglong2* B2 = (const ulonglong2*)wb2;
    const ulonglong2* XA = (const ulonglong2*)xa;
    const ulonglong2* XB = (const ulonglong2*)xb;
    int lane = threadIdx.x & 31;
    u64 acc[24] = {};
#pragma unroll
    for (int u = 0; u < 8; u++) {
        int i = lane + u * 32;
        ulonglong2 x0 = XA[i], x1 = XA[256 + i], x2 = XA[512 + i], x3 = XA[768 + i];
        ulonglong2 y0 = XB[i], y1 = XB[256 + i], y2 = XB[512 + i], y3 = XB[768 + i];
        ulonglong2 a;
        a = A0[i];
        acc[0] = f2fma(a.x, x0.x, acc[0]); acc[0] = f2fma(a.y, x0.y, acc[0]);
        acc[1] = f2fma(a.x, x1.x, acc[1]); acc[1] = f2fma(a.y, x1.y, acc[1]);
        acc[2] = f2fma(a.x, x2.x, acc[2]); acc[2] = f2fma(a.y, x2.y, acc[2]);
        acc[3] = f2fma(a.x, x3.x, acc[3]); acc[3] = f2fma(a.y, x3.y, acc[3]);
        a = A1[i];
        acc[4] = f2fma(a.x, x0.x, acc[4]); acc[4] = f2fma(a.y, x0.y, acc[4]);
        acc[5] = f2fma(a.x, x1.x, acc[5]); acc[5] = f2fma(a.y, x1.y, acc[5]);
        acc[6] = f2fma(a.x, x2.x, acc[6]); acc[6] = f2fma(a.y, x2.y, acc[6]);
        acc[7] = f2fma(a.x, x3.x, acc[7]); acc[7] = f2fma(a.y, x3.y, acc[7]);
        a = A2[i];
        acc[8] = f2fma(a.x, x0.x, acc[8]); acc[8] = f2fma(a.y, x0.y, acc[8]);
        acc[9] = f2fma(a.x, x1.x, acc[9]); acc[9] = f2fma(a.y, x1.y, acc[9]);
        acc[10]= f2fma(a.x, x2.x, acc[10]);acc[10]= f2fma(a.y, x2.y, acc[10]);
        acc[11]= f2fma(a.x, x3.x, acc[11]);acc[11]= f2fma(a.y, x3.y, acc[11]);
        a = B0[i];
        acc[12]= f2fma(a.x, y0.x, acc[12]);acc[12]= f2fma(a.y, y0.y, acc[12]);
        acc[13]= f2fma(a.x, y1.x, acc[13]);acc[13]= f2fma(a.y, y1.y, acc[13]);
        acc[14]= f2fma(a.x, y2.x, acc[14]);acc[14]= f2fma(a.y, y2.y, acc[14]);
        acc[15]= f2fma(a.x, y3.x, acc[15]);acc[15]= f2fma(a.y, y3.y, acc[15]);
        a = B1[i];
        acc[16]= f2fma(a.x, y0.x, acc[16]);acc[16]= f2fma(a.y, y0.y, acc[16]);
        acc[17]= f2fma(a.x, y1.x, acc[17]);acc[17]= f2fma(a.y, y1.y, acc[17]);
        acc[18]= f2fma(a.x, y2.x, acc[18]);acc[18]= f2fma(a.y, y2.y, acc[18]);
        acc[19]= f2fma(a.x, y3.x, acc[19]);acc[19]= f2fma(a.y, y3.y, acc[19]);
        a = B2[i];
        acc[20]= f2fma(a.x, y0.x, acc[20]);acc[20]= f2fma(a.y, y0.y, acc[20]);
        acc[21]= f2fma(a.x, y1.x, acc[21]);acc[21]= f2fma(a.y, y1.y, acc[21]);
        acc[22]= f2fma(a.x, y2.x, acc[22]);acc[22]= f2fma(a.y, y2.y, acc[22]);
        acc[23]= f2fma(a.x, y3.x, acc[23]);acc[23]= f2fma(a.y, y3.y, acc[23]);
    }
#pragma unroll
    for (int k = 0; k < 24; k++) out[k] = warp_sum(f2red(acc[k]));
}

// 3 weight rows x 4 batch vectors, packed f32x2 -> out[row*4+b]
__device__ __forceinline__ void sdot3x4p(const float* __restrict__ w0,
                                         const float* __restrict__ w1,
                                         const float* __restrict__ w2,
                                         const float* xs, float out[12]) {
    const ulonglong2* W0 = (const ulonglong2*)w0;
    const ulonglong2* W1 = (const ulonglong2*)w1;
    const ulonglong2* W2 = (const ulonglong2*)w2;
    const ulonglong2* X0 = (const ulonglong2*)xs;
    const ulonglong2* X1 = X0 + 256;
    const ulonglong2* X2 = X0 + 512;
    const ulonglong2* X3 = X0 + 768;
    int lane = threadIdx.x & 31;
    u64 acc[12] = {};
#pragma unroll
    for (int u = 0; u < 8; u++) {
        int i = lane + u * 32;
        ulonglong2 a0 = W0[i], a1 = W1[i], a2 = W2[i];
        ulonglong2 x0 = X0[i], x1 = X1[i], x2 = X2[i], x3 = X3[i];
        acc[0] = f2fma(a0.x, x0.x, acc[0]); acc[0] = f2fma(a0.y, x0.y, acc[0]);
        acc[1] = f2fma(a0.x, x1.x, acc[1]); acc[1] = f2fma(a0.y, x1.y, acc[1]);
        acc[2] = f2fma(a0.x, x2.x, acc[2]); acc[2] = f2fma(a0.y, x2.y, acc[2]);
        acc[3] = f2fma(a0.x, x3.x, acc[3]); acc[3] = f2fma(a0.y, x3.y, acc[3]);
        acc[4] = f2fma(a1.x, x0.x, acc[4]); acc[4] = f2fma(a1.y, x0.y, acc[4]);
        acc[5] = f2fma(a1.x, x1.x, acc[5]); acc[5] = f2fma(a1.y, x1.y, acc[5]);
        acc[6] = f2fma(a1.x, x2.x, acc[6]); acc[6] = f2fma(a1.y, x2.y, acc[6]);
        acc[7] = f2fma(a1.x, x3.x, acc[7]); acc[7] = f2fma(a1.y, x3.y, acc[7]);
        acc[8] = f2fma(a2.x, x0.x, acc[8]); acc[8] = f2fma(a2.y, x0.y, acc[8]);
        acc[9] = f2fma(a2.x, x1.x, acc[9]); acc[9] = f2fma(a2.y, x1.y, acc[9]);
        acc[10]= f2fma(a2.x, x2.x, acc[10]);acc[10]= f2fma(a2.y, x2.y, acc[10]);
        acc[11]= f2fma(a2.x, x3.x, acc[11]);acc[11]= f2fma(a2.y, x3.y, acc[11]);
    }
#pragma unroll
    for (int k = 0; k < 12; k++) out[k] = warp_sum(f2red(acc[k]));
}

__device__ __forceinline__ void sdot1x4p(const float* __restrict__ w,
                                         const float* xs, float out[4]) {
    const ulonglong2* W  = (const ulonglong2*)w;
    const ulonglong2* X0 = (const ulonglong2*)xs;
    const ulonglong2* X1 = X0 + 256;
    const ulonglong2* X2 = X0 + 512;
    const ulonglong2* X3 = X0 + 768;
    int lane = threadIdx.x & 31;
    u64 acc[4] = {};
#pragma unroll
    for (int u = 0; u < 8; u++) {
        int i = lane + u * 32;
        ulonglong2 wv = W[i];
        ulonglong2 x0 = X0[i], x1 = X1[i], x2 = X2[i], x3 = X3[i];
        acc[0] = f2fma(wv.x, x0.x, acc[0]); acc[0] = f2fma(wv.y, x0.y, acc[0]);
        acc[1] = f2fma(wv.x, x1.x, acc[1]); acc[1] = f2fma(wv.y, x1.y, acc[1]);
        acc[2] = f2fma(wv.x, x2.x, acc[2]); acc[2] = f2fma(wv.y, x2.y, acc[2]);
        acc[3] = f2fma(wv.x, x3.x, acc[3]); acc[3] = f2fma(wv.y, x3.y, acc[3]);
    }
#pragma unroll
    for (int k = 0; k < 4; k++) out[k] = warp_sum(f2red(acc[k]));
}

// grid barrier with integrated violation vote.
// Arrival word = (gen<<1)|block_vio in a parity-selected slot array.
// Returns global OR of all blocks' vio bits (uniform across the grid).
__device__ __forceinline__ int gbar_o(int nb, unsigned& gen, const int* s_vio) {
    gen++;
    int par = gen & 1;
    __syncthreads();                     // s_vio + smem writes visible
    if (threadIdx.x == 0) {
        int v = 0;
#pragma unroll
        for (int w = 0; w < 8; w++) v |= s_vio[w];
        st_rel(&g_slots[par][blockIdx.x * SLOT], (gen << 1) | (v ? 1u : 0u));
    }
    int got = 0;
    if ((int)threadIdx.x < nb) {
        unsigned x;
        do { x = ld_acq(&g_slots[par][threadIdx.x * SLOT]); } while ((x >> 1) < gen);
        got = (int)(x & 1u);
    }
    return __syncthreads_or(got);
}

// ---------------- kernels ----------------
__global__ void k_init() {
    int i = blockIdx.x * blockDim.x + threadIdx.x;
    for (int k = i; k < 2 * 256 * SLOT; k += gridDim.x * blockDim.x)
        ((unsigned*)g_slots)[k] = 0;
    for (int k = i; k < 2 * Bb * Hh; k += gridDim.x * blockDim.x) {
        g_h[k] = 0.f; g_l[k] = 0.f;
    }
}

__global__ void k_mac(const int* __restrict__ ids, const float* __restrict__ tok,
                      const float* __restrict__ pos, const float* __restrict__ pers,
                      const float* __restrict__ keys, const float* __restrict__ lvals,
                      const float* __restrict__ qw,
                      float* __restrict__ out_vals, float* __restrict__ out_idx) {
    __shared__ __align__(16) float sx[Dd];
    __shared__ __align__(16) float sq[KDim];
    __shared__ float ssim[Ss];
    __shared__ float rv[256];
    __shared__ int   ri[256];
    __shared__ int   s_top[TopK];

    int t = blockIdx.x, b = blockIdx.y;
    int tid = threadIdx.x;
    long row = (long)b * Tt + t;
    float* macrow = g_mac + row * MACW;

    int id = ids[b * Tt + t];
    for (int d = tid; d < Dd; d += 256) {
        float v = tok[(size_t)id * Dd + d] + pos[(size_t)t * Dd + d];
        sx[d] = v;
        macrow[d] = v;
    }
    for (int p = tid; p < Pp; p += 256) macrow[Dd + p] = pers[p];
    __syncthreads();

    int wid = tid >> 5, lane = tid & 31;
    for (int o = wid; o < KDim; o += 8) {
        const float4* W = (const float4*)(qw + (size_t)o * Dd);
        const float4* X = (const float4*)sx;
        float s = 0.f;
        for (int i = lane; i < Dd / 4; i += 32) s += d4(W[i], X[i]);
        s = warp_sum(s);
        if (lane == 0) sq[o] = s;
    }
    __syncthreads();

    for (int i = tid; i < Ss; i += 256) {
        const float4* Kr = (const float4*)(keys + (size_t)i * KDim);
        const float4* Q  = (const float4*)sq;
        float s = 0.f;
#pragma unroll
        for (int q = 0; q < 16; q++) s += d4(Kr[q], Q[q]);
        ssim[i] = s;
    }
    __syncthreads();

    for (int kk = 0; kk < TopK; kk++) {
        float bv = -1e30f; int bi2 = 0x7fffffff;
        for (int i = tid; i < Ss; i += 256) {
            float v = ssim[i];
            if (v > bv || (v == bv && i < bi2)) { bv = v; bi2 = i; }
        }
        rv[tid] = bv; ri[tid] = bi2;
        __syncthreads();
        for (int s = 128; s > 0; s >>= 1) {
            if (tid < s) {
                if (rv[tid + s] > rv[tid] ||
                    (rv[tid + s] == rv[tid] && ri[tid + s] < ri[tid])) {
                    rv[tid] = rv[tid + s]; ri[tid] = ri[tid + s];
                }
            }
            __syncthreads();
        }
        if (tid == 0) { s_top[kk] = ri[0]; ssim[ri[0]] = -1e38f; }
        __syncthreads();
    }

    for (int kk = 0; kk < TopK; kk++) {
        int ix = s_top[kk];
        for (int v = tid; v < VDim; v += 256) {
            float val = lvals[(size_t)ix * VDim + v];
            macrow[Dd + Pp + kk * VDim + v] = val;
            if (out_vals) out_vals[(row * TopK + kk) * VDim + v] = val;
        }
        if (tid == 0 && out_idx) out_idx[row * TopK + kk] = (float)ix;
    }
}

// C[M,N] = A[M,K] * B[N,K]^T ; epi=1 -> bias + exact gelu  (f32x2 inner)
__global__ void k_gemm(const float* __restrict__ A, const float* __restrict__ Bm,
                       const float* __restrict__ bias, float* __restrict__ C,
                       int M, int N, int Kd, int epi) {
    __shared__ __align__(16) float As[16][68];
    __shared__ __align__(16) float Bs[16][68];
    int tid = threadIdx.x;
    int tx = tid & 15, ty = tid >> 4;
    int q = tid & 3,  r  = tid >> 2;
    int m0 = blockIdx.y * 64, n0 = blockIdx.x * 64;
    u64 acc2[4][2] = {};
    for (int kt = 0; kt < Kd; kt += 16) {
        float4 av = *(const float4*)&A[(size_t)(m0 + r) * Kd + kt + q * 4];
        float4 bv = *(const float4*)&Bm[(size_t)(n0 + r) * Kd + kt + q * 4];
        As[q*4+0][r]=av.x; As[q*4+1][r]=av.y; As[q*4+2][r]=av.z; As[q*4+3][r]=av.w;
        Bs[q*4+0][r]=bv.x; Bs[q*4+1][r]=bv.y; Bs[q*4+2][r]=bv.z; Bs[q*4+3][r]=bv.w;
        __syncthreads();
#pragma unroll
        for (int kk = 0; kk < 16; kk++) {
            float4 a = *(const float4*)&As[kk][ty * 4];
            ulonglong2 bp = *(const ulonglong2*)&Bs[kk][tx * 4];
            u64 a0 = f2dup(a.x), a1 = f2dup(a.y), a2 = f2dup(a.z), a3 = f2dup(a.w);
            acc2[0][0] = f2fma(a0, bp.x, acc2[0][0]); acc2[0][1] = f2fma(a0, bp.y, acc2[0][1]);
            acc2[1][0] = f2fma(a1, bp.x, acc2[1][0]); acc2[1][1] = f2fma(a1, bp.y, acc2[1][1]);
            acc2[2][0] = f2fma(a2, bp.x, acc2[2][0]); acc2[2][1] = f2fma(a2, bp.y, acc2[2][1]);
            acc2[3][0] = f2fma(a3, bp.x, acc2[3][0]); acc2[3][1] = f2fma(a3, bp.y, acc2[3][1]);
        }
        __syncthreads();
    }
#pragma unroll
    for (int i = 0; i < 4; i++) {
        int m = m0 + ty * 4 + i;
#pragma unroll
        for (int jh = 0; jh < 2; jh++) {
            float lo, hi;
            asm("mov.b64 {%0, %1}, %2;" : "=f"(lo), "=f"(hi) : "l"(acc2[i][jh]));
            int n = n0 + tx * 4 + jh * 2;
            float v0 = lo, v1 = hi;
            if (epi) {
                v0 = gelu_exact(v0 + bias[n]);
                v1 = gelu_exact(v1 + bias[n + 1]);
            }
            C[(size_t)m * N + n]     = v0;
            C[(size_t)m * N + n + 1] = v1;
        }
    }
}

// C[3072][1024] = A(rows stride rstride, col offset coff) @ Bm[1024,1024]
__global__ void k_comb(const float* __restrict__ A, long rstride, long coff,
                       const float* __restrict__ Bm, float* __restrict__ C) {
    __shared__ __align__(16) float As[16][68];
    __shared__ __align__(16) float Bs[16][68];
    int tid = threadIdx.x;
    int tx = tid & 15, ty = tid >> 4;
    int q = tid & 3,  r  = tid >> 2;
    int rr = tid >> 4, cc = tid & 15;
    int n0 = blockIdx.x * 64, m0 = blockIdx.y * 64;
    float acc[4][4] = {};
    for (int d0 = 0; d0 < Hh; d0 += 16) {
        float4 av = *(const float4*)&A[(size_t)(m0 + r) * rstride + coff + d0 + q * 4];
        As[q*4+0][r]=av.x; As[q*4+1][r]=av.y; As[q*4+2][r]=av.z; As[q*4+3][r]=av.w;
        float4 bv = *(const float4*)&Bm[(size_t)(d0 + rr) * Hh + n0 + cc * 4];
        *(float4*)&Bs[rr][cc * 4] = bv;
        __syncthreads();
#pragma unroll
        for (int kk = 0; kk < 16; kk++) {
            float4 a = *(const float4*)&As[kk][ty * 4];
            float4 b = *(const float4*)&Bs[kk][tx * 4];
            acc[0][0]+=a.x*b.x; acc[0][1]+=a.x*b.y; acc[0][2]+=a.x*b.z; acc[0][3]+=a.x*b.w;
            acc[1][0]+=a.y*b.x; acc[1][1]+=a.y*b.y; acc[1][2]+=a.y*b.z; acc[1][3]+=a.y*b.w;
            acc[2][0]+=a.z*b.x; acc[2][1]+=a.z*b.y; acc[2][2]+=a.z*b.z; acc[2][3]+=a.z*b.w;
            acc[3][0]+=a.w*b.x; acc[3][1]+=a.w*b.y; acc[3][2]+=a.w*b.z; acc[3][3]+=a.w*b.w;
        }
        __syncthreads();
    }
#pragma unroll
    for (int i = 0; i < 4; i++)
#pragma unroll
        for (int j = 0; j < 4; j++)
            C[(size_t)(m0 + ty * 4 + i) * Hh + n0 + tx * 4 + j] = acc[i][j];
}

// out[r] = addb[r] + dot(W[r*rstride+coff .. +1024], v)
__global__ void k_vdot(const float* __restrict__ W, long rstride, long coff,
                       const float* __restrict__ v, const float* __restrict__ addb,
                       float* __restrict__ out) {
    int r = (blockIdx.x * blockDim.x + threadIdx.x) >> 5;
    if (r >= 3 * Hh) return;
    const float4* Wr = (const float4*)(W + (size_t)r * rstride + coff);
    const float4* X  = (const float4*)v;
    int lane = threadIdx.x & 31;
    float s = 0.f;
    for (int i = lane; i < 256; i += 32) s += d4(Wr[i], X[i]);
    s = warp_sum(s);
    if (lane == 0) out[r] = (addb ? addb[r] : 0.f) + s;
}

// ---- persistent recurrence: 256 threads, warp per hidden unit, fused dots ----
__global__ __launch_bounds__(256, 1)
void k_seq(int nb,
           const float* __restrict__ hWi, const float* __restrict__ hbi,
           const float* __restrict__ hWh, const float* __restrict__ hbh,
           const float* __restrict__ lWi,
           const float* __restrict__ lWh, const float* __restrict__ lbh,
           const float* __restrict__ l2ow, const float* __restrict__ l2ob) {
    __shared__ __align__(16) float se[Bb * 1024];   // enc input, lives whole hstep
    __shared__ __align__(16) float sx[Bb * 1024];   // current l (kept warm)
    __shared__ __align__(16) float sy[Bb * 1024];
    __shared__ int s_vio[8];

    int tid  = threadIdx.x;
    int lane = tid & 31;
    int wid  = tid >> 5;                  // 0..7
    int j    = blockIdx.x * UPB + wid;    // hidden unit (warp 7 inactive)
    bool act = (wid < UPB) && (j < Hh);
    unsigned gen = 0;
    int hc = 0, lc = 0;
    if (lane == 0) s_vio[wid] = 0;

    float bir=0, biz=0, bin_=0, bhr=0, bhz=0, bhn=0;
    float gbr=0, gbz=0, gbn=0, lbr=0, lbz=0, lbn=0, l2b=0;
    if (act) {
        bir = hbi[j]; biz = hbi[j + Hh]; bin_ = hbi[j + 2 * Hh];
        bhr = hbh[j]; bhz = hbh[j + Hh]; bhn  = hbh[j + 2 * Hh];
        gbr = g_bcomb[j]; gbz = g_bcomb[j + Hh]; gbn = g_bcomb[j + 2 * Hh];
        lbr = lbh[j]; lbz = lbh[j + Hh]; lbn = lbh[j + 2 * Hh];
        l2b = l2ob[j];
    }

    // seed sx with l0 (= zeros); thereafter every P5 / l-iteration keeps it current
    stage(sx, g_l + lc * Bb * Hh, Hh);

    for (int t = 0; t < Tt; t++) {
        for (int hs = 0; hs < 2; hs++) {
            const float* ein; float* eout; long ebs, obs;
            if (hs == 0) { ein = g_enc + (size_t)t * Dd; ebs = (long)Tt * Dd;
                           eout = g_enc_cur;              obs = Dd; }
            else         { ein = g_enc_cur;               ebs = Dd;
                           eout = g_enc + (size_t)t * Dd; obs = (long)Tt * Dd; }

            // ---- P1: h-GRU + gil enc-part (fused: one pass over se) ----
            stage(se, ein, ebs);
            stage(sy, g_h + hc * Bb * Hh, Hh);
            __syncthreads();

            float gpart[12];
            if (act) {
                float sg[24], shh[12];
                sdot6x4p(hWi + (size_t)j * Dd, hWi + (size_t)(j + Hh) * Dd,
                         hWi + (size_t)(j + 2 * Hh) * Dd,
                         lWi + (size_t)j * 2048, lWi + (size_t)(j + Hh) * 2048,
                         lWi + (size_t)(j + 2 * Hh) * 2048, se, sg);
                sdot3x4p(hWh + (size_t)j * Hh, hWh + (size_t)(j + Hh) * Hh,
                         hWh + (size_t)(j + 2 * Hh) * Hh, sy, shh);
#pragma unroll
                for (int k = 0; k < 12; k++) gpart[k] = sg[12 + k];
                if (lane == 0) {
#pragma unroll
                    for (int b = 0; b < Bb; b++) {
                        float r = sigm((sg[b] + bir) + (shh[b] + bhr));
                        float z = sigm((sg[4+b] + biz) + (shh[4+b] + bhz));
                        float n = tanhf((sg[8+b] + bin_) + r * (shh[8+b] + bhn));
                        float hp = sy[b * 1024 + j];
                        g_h[(hc ^ 1) * Bb * Hh + b * Hh + j] = (1.f - z) * n + z * hp;
                    }
                }
            }
            gbar_o(nb, gen, s_vio);
            hc ^= 1;

            // ---- P2: gil + fused l-iter 0 (sx already holds current l) ----
            stage(sy, g_h + hc * Bb * Hh, Hh);
            if (lane == 0) s_vio[wid] = 0;
            __syncthreads();

            float gr[4], gz[4], gn2[4];
            if (act) {
                float d2[24];
                sdot33x4p(g_wcomb + (size_t)j * Hh, g_wcomb + (size_t)(j + Hh) * Hh,
                          g_wcomb + (size_t)(j + 2 * Hh) * Hh, sy,
                          lWh + (size_t)j * Hh, lWh + (size_t)(j + Hh) * Hh,
                          lWh + (size_t)(j + 2 * Hh) * Hh, sx, d2);
                if (lane == 0) {
                    bool vio = false;
#pragma unroll
                    for (int b = 0; b < Bb; b++) {
                        gr[b]  = gpart[b]     + d2[b]     + gbr;
                        gz[b]  = gpart[4 + b] + d2[4 + b] + gbz;
                        gn2[b] = gpart[8 + b] + d2[8 + b] + gbn;
                        float r = sigm(gr[b] + (d2[12 + b] + lbr));
                        float z = sigm(gz[b] + (d2[16 + b] + lbz));
                        float n = tanhf(gn2[b] + r * (d2[20 + b] + lbn));
                        float old = sx[b * 1024 + j];
                        float nv = (1.f - z) * n + z * old;
                        if (fabsf(nv - old) > 1e-4f + 1e-5f * fabsf(old)) vio = true;
                        g_l[(lc ^ 1) * Bb * Hh + b * Hh + j] = nv;
                    }
                    if (vio) s_vio[wid] = 1;
                }
            }
            int conv = (gbar_o(nb, gen, s_vio) == 0);
            lc ^= 1;

            // ---- remaining l-iterations ----
            for (int it = 1; it < 4 && !conv; it++) {
                stage(sx, g_l + lc * Bb * Hh, Hh);
                if (lane == 0) s_vio[wid] = 0;
                __syncthreads();
                if (act) {
                    float shl[12];
                    sdot3x4p(lWh + (size_t)j * Hh, lWh + (size_t)(j + Hh) * Hh,
                             lWh + (size_t)(j + 2 * Hh) * Hh, sx, shl);
                    if (lane == 0) {
                        bool vio = false;
#pragma unroll
                        for (int b = 0; b < Bb; b++) {
                            float r = sigm(gr[b] + (shl[b] + lbr));
                            float z = sigm(gz[b] + (shl[4 + b] + lbz));
                            float n = tanhf(gn2[b] + r * (shl[8 + b] + lbn));
                            float old = sx[b * 1024 + j];
                            float nv = (1.f - z) * n + z * old;
                            if (fabsf(nv - old) > 1e-4f + 1e-5f * fabsf(old)) vio = true;
                            g_l[(lc ^ 1) * Bb * Hh + b * Hh + j] = nv;
                        }
                        if (vio) s_vio[wid] = 1;
                    }
                }
                conv = (gbar_o(nb, gen, s_vio) == 0);
                lc ^= 1;
            }

            // ---- P5: enc = enc + l @ l2o^T + b (enc still in se) ----
            stage(sx, g_l + lc * Bb * Hh, Hh);
            if (lane == 0) s_vio[wid] = 0;
            __syncthreads();
            if (act) {
                float s[4];
                sdot1x4p(l2ow + (size_t)j * Hh, sx, s);
                if (lane == 0)
#pragma unroll
                    for (int b = 0; b < Bb; b++)
                        eout[(long)b * obs + j] = se[b * 1024 + j] + s[b] + l2b;
            }
            gbar_o(nb, gen, s_vio);
        }
    }
}

// in-place layernorm of g_enc rows
__global__ void k_ln(const float* __restrict__ gam, const float* __restrict__ bet) {
    __shared__ float red[256];
    int row = blockIdx.x;
    float* x = g_enc + (size_t)row * Dd;
    int tid = threadIdx.x;
    float ls = 0.f;
    for (int i = tid; i < Dd; i += 256) ls += x[i];
    red[tid] = ls; __syncthreads();
    for (int s = 128; s > 0; s >>= 1) { if (tid < s) red[tid] += red[tid + s]; __syncthreads(); }
    float mu = red[0] / Dd;
    __syncthreads();
    float lv = 0.f;
    for (int i = tid; i < Dd; i += 256) { float dxx = x[i] - mu; lv += dxx * dxx; }
    red[tid] = lv; __syncthreads();
    for (int s = 128; s > 0; s >>= 1) { if (tid < s) red[tid] += red[tid + s]; __syncthreads(); }
    float rstd = rsqrtf(red[0] / Dd + 1e-5f);
    for (int i = tid; i < Dd; i += 256) x[i] = (x[i] - mu) * rstd * gam[i] + bet[i];
}

// ---------------- host ----------------
extern "C" void kernel_launch(void* const* d_in, const int* in_sizes, int n_in,
                              void* d_out, int out_size) {
    const int*   ids   = (const int*)d_in[0];
    const float* tok   = (const float*)d_in[1];
    const float* pos   = (const float*)d_in[2];
    const float* pers  = (const float*)d_in[3];
    const float* keys  = (const float*)d_in[4];
    const float* lvals = (const float*)d_in[5];
    const float* qw    = (const float*)d_in[6];
    const float* ipw   = (const float*)d_in[7];
    const float* ipb   = (const float*)d_in[8];
    const float* hWi   = (const float*)d_in[9];
    const float* hbi   = (const float*)d_in[10];
    const float* hWh   = (const float*)d_in[11];
    const float* hbh   = (const float*)d_in[12];
    const float* h2cw  = (const float*)d_in[13];
    const float* h2cb  = (const float*)d_in[14];
    const float* lWi   = (const float*)d_in[15];
    const float* lbi   = (const float*)d_in[16];
    const float* lWh   = (const float*)d_in[17];
    const float* lbh   = (const float*)d_in[18];
    const float* l2ow  = (const float*)d_in[19];
    const float* l2ob  = (const float*)d_in[20];
    const float* lng   = (const float*)d_in[21];
    const float* lnb   = (const float*)d_in[22];
    (void)in_sizes; (void)n_in;

    float* out = (float*)d_out;
    long LOGN = (long)Bb * Tt * Vv;
    long VALN = (long)Bb * Tt * TopK * VDim;
    long IDXN = (long)Bb * Tt * TopK;
    float* ov = nullptr; float* oi = nullptr;
    if ((long)out_size >= LOGN + VALN + IDXN) {
        ov = out + LOGN;
        oi = out + LOGN + VALN;
    }

    float *encp, *macp, *wcp, *bcp;
    cudaGetSymbolAddress((void**)&encp, g_enc);
    cudaGetSymbolAddress((void**)&macp, g_mac);
    cudaGetSymbolAddress((void**)&wcp,  g_wcomb);
    cudaGetSymbolAddress((void**)&bcp,  g_bcomb);

    int sm = 148;
    cudaDeviceGetAttribute(&sm, cudaDevAttrMultiProcessorCount, 0);
    int nb = sm;
    if (nb * UPB < Hh) nb = (Hh + UPB - 1) / UPB;
    if (nb > 256) nb = 256;

    k_init<<<32, 256>>>();

    { dim3 g(Tt, Bb); k_mac<<<g, 256>>>(ids, tok, pos, pers, keys, lvals, qw, ov, oi); }

    // enc0 = gelu(mac @ in_proj^T + b)
    k_gemm<<<dim3(Dd / 64, (Bb * Tt) / 64), 256>>>(macp, ipw, ipb, encp,
                                                   Bb * Tt, Dd, MACW, 1);

    // combined l-input weights: W_comb = lWi2 @ h2c, b_comb = lbi + lWi2 @ h2cb
    k_comb<<<dim3(Hh / 64, (3 * Hh) / 64), 256>>>(lWi, 2048, 1024, h2cw, wcp);
    k_vdot<<<384, 256>>>(lWi, 2048, 1024, h2cb, lbi, bcp);

    // the whole recurrence: one persistent kernel (256 threads, warp per unit)
    k_seq<<<nb, 256>>>(nb, hWi, hbi, hWh, hbh, lWi, lWh, lbh, l2ow, l2ob);

    k_ln<<<Bb * Tt, 256>>>(lng, lnb);

    // logits = y @ tok_emb^T
    k_gemm<<<dim3(Vv / 64, (Bb * Tt) / 64), 256>>>(encp, tok, nullptr, out,
                                                   Bb * Tt, Vv, Dd, 0);
}